// round 6
// baseline (speedup 1.0000x reference)
#include <cuda_runtime.h>
#include <cuda_bf16.h>
#include <math.h>
#include <stdint.h>

// ---------------------------------------------------------------------------
// Swin block: B=32, H=W=128, C=128, WS=2, SS=1, NH=8, HD=16
// 3 fused kernels: [LN1+qkv-GEMM] -> [attn+proj-GEMM] -> [LN2+MLP1+MLP2]
// GEMMs: mma.sync bf16 hi/lo x3 (emulated fp32), baseline PTX.
// ---------------------------------------------------------------------------

#define TOK   524288
#define NWIN  131072

typedef __nv_bfloat16 bf16;

// persistent scratch
__device__ float g_qkv[(size_t)TOK * 384];   // q scaled; window-ordered rows
__device__ float g_h2 [(size_t)TOK * 128];   // x + attn-proj (original order)
// weights transposed to [N,K] + hi/lo split
__device__ bf16  g_wqh[384 * 128], g_wql[384 * 128];
__device__ bf16  g_wph[128 * 128], g_wpl[128 * 128];
__device__ bf16  g_w1h[256 * 128], g_w1l[256 * 128];
__device__ bf16  g_w2h[128 * 256], g_w2l[128 * 256];

// ---------------------------------------------------------------------------
__device__ __forceinline__ uint32_t smem_u32(const void* p) {
    uint32_t a;
    asm("{ .reg .u64 t; cvta.to.shared.u64 t, %1; cvt.u32.u64 %0, t; }"
        : "=r"(a) : "l"(p));
    return a;
}

#define SWZ128(o) ((o) ^ (((o) >> 3) & 0x70))

#define CP_ASYNC16(dst, src) \
    asm volatile("cp.async.cg.shared.global [%0], [%1], 16;" \
                 :: "r"(dst), "l"(src) : "memory")
#define CP_COMMIT()   asm volatile("cp.async.commit_group;" ::: "memory")
#define CP_WAIT0()    asm volatile("cp.async.wait_group 0;" ::: "memory")

__device__ __forceinline__ void ldsm4(uint32_t r[4], uint32_t addr) {
    asm volatile("ldmatrix.sync.aligned.m8n8.x4.shared.b16 {%0,%1,%2,%3}, [%4];"
                 : "=r"(r[0]), "=r"(r[1]), "=r"(r[2]), "=r"(r[3]) : "r"(addr));
}

__device__ __forceinline__ void mma_bf16(float4& d, const uint32_t a[4],
                                         const uint32_t b[2]) {
    asm volatile(
        "mma.sync.aligned.m16n8k16.row.col.f32.bf16.bf16.f32 "
        "{%0,%1,%2,%3}, {%4,%5,%6,%7}, {%8,%9}, {%0,%1,%2,%3};"
        : "+f"(d.x), "+f"(d.y), "+f"(d.z), "+f"(d.w)
        : "r"(a[0]), "r"(a[1]), "r"(a[2]), "r"(a[3]), "r"(b[0]), "r"(b[1]));
}

__device__ __forceinline__ int orig_of(int r) {
    int win = r >> 2, s = r & 3;
    int b  = win >> 12;
    int w  = win & 4095;
    int wh = w >> 6, ww = w & 63;
    int ii = ((wh << 1) + (s >> 1) + 1) & 127;
    int jj = ((ww << 1) + (s & 1) + 1) & 127;
    return (b << 14) + (ii << 7) + jj;
}

__device__ __forceinline__ uint32_t pk2(float a, float b) {
    __nv_bfloat162 t = __floats2bfloat162_rn(a, b);
    return *(uint32_t*)&t;
}
__device__ __forceinline__ float bhi(float v) {
    return __bfloat162float(__float2bfloat16(v));
}

// ---------------------------------------------------------------------------
// Shared building blocks
// ---------------------------------------------------------------------------

// LayerNorm 128 rows of in (optionally gathered) -> hi/lo bf16 into SW128
// operand region at aOff (2 k-chunks of 32KB: hi 16KB + lo 16KB each).
template <bool GATHER>
__device__ __forceinline__ void ln_to_smem(
    const float* __restrict__ in, const float* __restrict__ gamma,
    const float* __restrict__ beta, char* smem, uint32_t aOff, int rowBase)
{
    const int tid = threadIdx.x, lane = tid & 31, wid = tid >> 5;
    const float4 g = *(const float4*)(gamma + lane * 4);
    const float4 b = *(const float4*)(beta  + lane * 4);
    const uint32_t colOff = (uint32_t)((lane & 15) * 8);
    char* dhi = smem + aOff + (lane >> 4) * 32768;
#pragma unroll 4
    for (int r = wid; r < 128; r += 8) {
        int src = GATHER ? orig_of(rowBase + r) : (rowBase + r);
        float4 v = __ldg((const float4*)(in + (size_t)src * 128 + lane * 4));
        float s = v.x + v.y + v.z + v.w;
        float q = v.x * v.x + v.y * v.y + v.z * v.z + v.w * v.w;
#pragma unroll
        for (int o = 16; o; o >>= 1) {
            s += __shfl_xor_sync(0xffffffffu, s, o);
            q += __shfl_xor_sync(0xffffffffu, q, o);
        }
        float mean = s * (1.0f / 128.0f);
        float rstd = rsqrtf(q * (1.0f / 128.0f) - mean * mean + 1e-5f);
        float o0 = (v.x - mean) * rstd * g.x + b.x;
        float o1 = (v.y - mean) * rstd * g.y + b.y;
        float o2 = (v.z - mean) * rstd * g.z + b.z;
        float o3 = (v.w - mean) * rstd * g.w + b.w;
        float h0 = bhi(o0), h1 = bhi(o1), h2 = bhi(o2), h3 = bhi(o3);
        // FULL-offset swizzle: row bits participate in the XOR pattern.
        uint32_t o16 = SWZ128((uint32_t)(r * 128) + colOff);
        *(uint2*)(dhi + o16)         = make_uint2(pk2(h0, h1), pk2(h2, h3));
        *(uint2*)(dhi + 16384 + o16) = make_uint2(pk2(o0 - h0, o1 - h1),
                                                  pk2(o2 - h2, o3 - h3));
    }
}

// cp.async one 128x64 bf16 hi/lo weight chunk into SW128 region at dstBase.
__device__ __forceinline__ void load_w_chunk(
    uint32_t dstBase, const bf16* __restrict__ hi, const bf16* __restrict__ lo,
    int rowOff, int kOff, int kStride)
{
    const int tid = threadIdx.x;
    const int c16 = tid & 7;
#pragma unroll
    for (int it = 0; it < 4; it++) {
        int row = (tid >> 3) + it * 32;
        uint32_t d = dstBase + SWZ128((uint32_t)(row * 128 + c16 * 16));
        const size_t s = (size_t)(rowOff + row) * kStride + kOff + c16 * 8;
        CP_ASYNC16(d, hi + s);
        CP_ASYNC16(d + 16384, lo + s);
    }
    CP_COMMIT();
}

// One k64 chunk of warp MMA: acc += A x B (3-pass hi/lo).
__device__ __forceinline__ void mma_chunk(
    float4 (&acc)[4][4], uint32_t aBase, uint32_t bBase)
{
    const int lane = threadIdx.x & 31, wid = threadIdx.x >> 5;
    const int warp_m = wid >> 2, warp_n = wid & 3;
    const int arow = warp_m * 64 + (lane & 15);
    const int akb  = (lane >> 4) * 8;
    const int brow = warp_n * 32 + ((lane >> 4) & 1) * 8 + (lane & 7);
    const int bkb  = ((lane >> 3) & 1) * 8;
#pragma unroll
    for (int ks = 0; ks < 4; ks++) {
        const int k0 = ks * 16;
        uint32_t bh[2][4], bl[2][4];
#pragma unroll
        for (int i = 0; i < 2; i++) {
            uint32_t boff = SWZ128((uint32_t)((brow + i * 16) * 128
                                              + (k0 + bkb) * 2));
            ldsm4(bh[i], bBase + boff);
            ldsm4(bl[i], bBase + 16384 + boff);
        }
#pragma unroll
        for (int mt = 0; mt < 4; mt++) {
            uint32_t aoff = SWZ128((uint32_t)((arow + mt * 16) * 128
                                              + (k0 + akb) * 2));
            uint32_t ah[4], al[4];
            ldsm4(ah, aBase + aoff);
            ldsm4(al, aBase + 16384 + aoff);
#pragma unroll
            for (int nt = 0; nt < 4; nt++) {
                mma_bf16(acc[mt][nt], ah, &bh[nt >> 1][(nt & 1) * 2]);
                mma_bf16(acc[mt][nt], ah, &bl[nt >> 1][(nt & 1) * 2]);
                mma_bf16(acc[mt][nt], al, &bh[nt >> 1][(nt & 1) * 2]);
            }
        }
    }
}

// ---------------------------------------------------------------------------
// Weight transpose + split: w[K,N] fp32 -> hi/lo [N,K] bf16
// ---------------------------------------------------------------------------
__global__ void wconv(const float* __restrict__ w, int K, int N,
                      bf16* __restrict__ hi, bf16* __restrict__ lo)
{
    int idx = blockIdx.x * 256 + threadIdx.x;
    if (idx >= N * K) return;
    int n = idx / K, k = idx - n * K;
    float v = w[(size_t)k * N + n];
    float h = bhi(v);
    hi[idx] = __float2bfloat16(v);
    lo[idx] = __float2bfloat16(v - h);
}

// ---------------------------------------------------------------------------
// Kernel 1: LN1 (+shift/window gather) fused into qkv GEMM.  3 N-passes.
// smem: A 64KB @0 | B 32KB @65536  -> 96KB
// ---------------------------------------------------------------------------
__global__ __launch_bounds__(256) void qkv_kernel(
    const float* __restrict__ x, const float* __restrict__ g1,
    const float* __restrict__ b1,
    const bf16* __restrict__ wqh, const bf16* __restrict__ wql,
    const float* __restrict__ qkv_b, float* __restrict__ qkv)
{
    extern __shared__ char smem[];
    const uint32_t sb = smem_u32(smem);
    const int tid = threadIdx.x, lane = tid & 31, wid = tid >> 5;
    const int warp_m = wid >> 2, warp_n = wid & 3;
    const int rowBase = blockIdx.x << 7;

    ln_to_smem<true>(x, g1, b1, smem, 0, rowBase);

    const int r4 = lane >> 2, c2 = (lane & 3) * 2;

#pragma unroll
    for (int npass = 0; npass < 3; npass++) {
        float4 acc[4][4];
#pragma unroll
        for (int i = 0; i < 4; i++)
#pragma unroll
            for (int j = 0; j < 4; j++) acc[i][j] = make_float4(0, 0, 0, 0);
#pragma unroll
        for (int kc = 0; kc < 2; kc++) {
            __syncthreads();   // B buffer free (also orders LN writes)
            load_w_chunk(sb + 65536, wqh, wql, npass * 128, kc * 64, 128);
            CP_WAIT0();
            __syncthreads();
            mma_chunk(acc, sb + kc * 32768, sb + 65536);
        }
        const float scale = (npass == 0) ? 0.25f : 1.0f;
#pragma unroll
        for (int mt = 0; mt < 4; mt++)
#pragma unroll
            for (int half = 0; half < 2; half++) {
                const int gr = rowBase + warp_m * 64 + mt * 16 + r4 + half * 8;
#pragma unroll
                for (int nt = 0; nt < 4; nt++) {
                    const int col = npass * 128 + warp_n * 32 + nt * 8 + c2;
                    float v0 = half ? acc[mt][nt].z : acc[mt][nt].x;
                    float v1 = half ? acc[mt][nt].w : acc[mt][nt].y;
                    v0 = (v0 + __ldg(qkv_b + col)) * scale;
                    v1 = (v1 + __ldg(qkv_b + col + 1)) * scale;
                    *(float2*)(qkv + (size_t)gr * 384 + col) = make_float2(v0, v1);
                }
            }
    }
}

// ---------------------------------------------------------------------------
// Kernel 2: window attention (qkv from gmem) fused into proj GEMM + residual.
// smem: O 64KB @0 | Wp 32KB @65536  -> 96KB
// ---------------------------------------------------------------------------
__global__ __launch_bounds__(256) void attnproj_kernel(
    const float* __restrict__ qkv, const float* __restrict__ rpb,
    const bf16* __restrict__ wph, const bf16* __restrict__ wpl,
    const float* __restrict__ proj_b, const float* __restrict__ x,
    float* __restrict__ h2)
{
    extern __shared__ char smem[];
    const uint32_t sb = smem_u32(smem);
    const int tid = threadIdx.x, lane = tid & 31, wid = tid >> 5;
    const int warp_m = wid >> 2, warp_n = wid & 3;
    const int rowBase = blockIdx.x << 7;
    const int win0    = blockIdx.x << 5;
    const int h = lane >> 2, i = lane & 3;
    const int dy1 = i >> 1, dx1 = i & 1;

    // ---- attention: each warp handles 4 windows -----------------------------
#pragma unroll
    for (int t = 0; t < 4; t++) {
        const int wl  = wid * 4 + t;          // local window 0..31
        const int win = win0 + wl;
        const int w   = win & 4095;
        const bool mr = ((w >> 6) == 63);
        const bool mc = ((w & 63) == 63);
        const float* base = qkv + (size_t)win * (4 * 384);

        float q[16];
        const float* qp = base + i * 384 + h * 16;
#pragma unroll
        for (int d4 = 0; d4 < 4; d4++) {
            float4 v = __ldg((const float4*)(qp + d4 * 4));
            q[d4 * 4 + 0] = v.x; q[d4 * 4 + 1] = v.y;
            q[d4 * 4 + 2] = v.z; q[d4 * 4 + 3] = v.w;
        }
        float s[4];
#pragma unroll
        for (int j = 0; j < 4; j++) {
            const float* kp = base + j * 384 + 128 + h * 16;
            float a = 0.0f;
#pragma unroll
            for (int d4 = 0; d4 < 4; d4++) {
                float4 v = __ldg((const float4*)(kp + d4 * 4));
                a += q[d4 * 4 + 0] * v.x + q[d4 * 4 + 1] * v.y
                   + q[d4 * 4 + 2] * v.z + q[d4 * 4 + 3] * v.w;
            }
            int dy2 = j >> 1, dx2 = j & 1;
            bool ok = (!mr || dy1 == dy2) && (!mc || dx1 == dx2);
            s[j] = a + __ldg(rpb + ((dy1 - dy2 + 1) * 3 + (dx1 - dx2 + 1)) * 8 + h)
                 + (ok ? 0.0f : -100.0f);
        }
        float mx = fmaxf(fmaxf(s[0], s[1]), fmaxf(s[2], s[3]));
        float p[4], sum = 0.0f;
#pragma unroll
        for (int j = 0; j < 4; j++) { p[j] = expf(s[j] - mx); sum += p[j]; }
        float inv = 1.0f / sum;

        float ov[16];
#pragma unroll
        for (int d = 0; d < 16; d++) ov[d] = 0.0f;
#pragma unroll
        for (int j = 0; j < 4; j++) {
            const float* vp = base + j * 384 + 256 + h * 16;
            float pj = p[j] * inv;
#pragma unroll
            for (int d4 = 0; d4 < 4; d4++) {
                float4 v = __ldg((const float4*)(vp + d4 * 4));
                ov[d4 * 4 + 0] += pj * v.x; ov[d4 * 4 + 1] += pj * v.y;
                ov[d4 * 4 + 2] += pj * v.z; ov[d4 * 4 + 3] += pj * v.w;
            }
        }
        // store o hi/lo into SW128 operand region (row = wl*4+i, ch = h*16+d)
        const int row = wl * 4 + i;
#pragma unroll
        for (int d4 = 0; d4 < 4; d4++) {
            const int ch = h * 16 + d4 * 4;
            char* dst = smem + (ch >> 6) * 32768;
            uint32_t o16 = SWZ128((uint32_t)(row * 128 + (ch & 63) * 2));
            float a0 = ov[d4 * 4], a1 = ov[d4 * 4 + 1],
                  a2 = ov[d4 * 4 + 2], a3 = ov[d4 * 4 + 3];
            float h0 = bhi(a0), h1 = bhi(a1), h2v = bhi(a2), h3 = bhi(a3);
            *(uint2*)(dst + o16)         = make_uint2(pk2(h0, h1), pk2(h2v, h3));
            *(uint2*)(dst + 16384 + o16) = make_uint2(pk2(a0 - h0, a1 - h1),
                                                      pk2(a2 - h2v, a3 - h3));
        }
    }

    // ---- proj GEMM ----------------------------------------------------------
    float4 acc[4][4];
#pragma unroll
    for (int a = 0; a < 4; a++)
#pragma unroll
        for (int j = 0; j < 4; j++) acc[a][j] = make_float4(0, 0, 0, 0);
#pragma unroll
    for (int kc = 0; kc < 2; kc++) {
        __syncthreads();
        load_w_chunk(sb + 65536, wph, wpl, 0, kc * 64, 128);
        CP_WAIT0();
        __syncthreads();
        mma_chunk(acc, sb + kc * 32768, sb + 65536);
    }

    const int r4 = lane >> 2, c2 = (lane & 3) * 2;
#pragma unroll
    for (int mt = 0; mt < 4; mt++)
#pragma unroll
        for (int half = 0; half < 2; half++) {
            const int gr = rowBase + warp_m * 64 + mt * 16 + r4 + half * 8;
            const size_t outRow = (size_t)orig_of(gr);
#pragma unroll
            for (int nt = 0; nt < 4; nt++) {
                const int col = warp_n * 32 + nt * 8 + c2;
                float v0 = half ? acc[mt][nt].z : acc[mt][nt].x;
                float v1 = half ? acc[mt][nt].w : acc[mt][nt].y;
                const float2 sk = *(const float2*)(x + outRow * 128 + col);
                v0 += __ldg(proj_b + col) + sk.x;
                v1 += __ldg(proj_b + col + 1) + sk.y;
                *(float2*)(h2 + outRow * 128 + col) = make_float2(v0, v1);
            }
        }
}

// ---------------------------------------------------------------------------
// Kernel 3: LN2 + MLP1(GELU) + MLP2 + residual, fully fused.
// smem: L2A 64KB @0 | M1 128KB @65536 | W 32KB @196608 -> 224KB
// ---------------------------------------------------------------------------
__global__ __launch_bounds__(256) void mlp_kernel(
    const float* __restrict__ h2, const float* __restrict__ g2,
    const float* __restrict__ b2,
    const bf16* __restrict__ w1h, const bf16* __restrict__ w1l,
    const float* __restrict__ bb1,
    const bf16* __restrict__ w2h, const bf16* __restrict__ w2l,
    const float* __restrict__ bb2, float* __restrict__ out)
{
    extern __shared__ char smem[];
    const uint32_t sb = smem_u32(smem);
    const int tid = threadIdx.x, lane = tid & 31, wid = tid >> 5;
    const int warp_m = wid >> 2, warp_n = wid & 3;
    const int rowBase = blockIdx.x << 7;
    const int r4 = lane >> 2, c2 = (lane & 3) * 2;

    ln_to_smem<false>(h2, g2, b2, smem, 0, rowBase);

    // ---- mlp1: m1 = gelu(l2 @ W1 + b1), 2 N-passes into smem ---------------
#pragma unroll
    for (int npass = 0; npass < 2; npass++) {
        float4 acc[4][4];
#pragma unroll
        for (int a = 0; a < 4; a++)
#pragma unroll
            for (int j = 0; j < 4; j++) acc[a][j] = make_float4(0, 0, 0, 0);
#pragma unroll
        for (int kc = 0; kc < 2; kc++) {
            __syncthreads();
            load_w_chunk(sb + 196608, w1h, w1l, npass * 128, kc * 64, 128);
            CP_WAIT0();
            __syncthreads();
            mma_chunk(acc, sb + kc * 32768, sb + 196608);
        }
#pragma unroll
        for (int mt = 0; mt < 4; mt++)
#pragma unroll
            for (int half = 0; half < 2; half++) {
                const int row = warp_m * 64 + mt * 16 + r4 + half * 8;
#pragma unroll
                for (int nt = 0; nt < 4; nt++) {
                    const int ch = npass * 128 + warp_n * 32 + nt * 8 + c2;
                    float v0 = half ? acc[mt][nt].z : acc[mt][nt].x;
                    float v1 = half ? acc[mt][nt].w : acc[mt][nt].y;
                    v0 += __ldg(bb1 + ch);
                    v1 += __ldg(bb1 + ch + 1);
                    v0 = v0 * normcdff(v0);
                    v1 = v1 * normcdff(v1);
                    float h0 = bhi(v0), h1 = bhi(v1);
                    char* dst = smem + 65536 + (ch >> 6) * 32768;
                    uint32_t o16 = SWZ128((uint32_t)(row * 128 + (ch & 63) * 2));
                    *(uint32_t*)(dst + o16)         = pk2(h0, h1);
                    *(uint32_t*)(dst + 16384 + o16) = pk2(v0 - h0, v1 - h1);
                }
            }
    }

    // ---- mlp2: out = m1 @ W2 + b2 + h2 --------------------------------------
    float4 acc[4][4];
#pragma unroll
    for (int a = 0; a < 4; a++)
#pragma unroll
        for (int j = 0; j < 4; j++) acc[a][j] = make_float4(0, 0, 0, 0);
#pragma unroll
    for (int kc = 0; kc < 4; kc++) {
        __syncthreads();
        load_w_chunk(sb + 196608, w2h, w2l, 0, kc * 64, 256);
        CP_WAIT0();
        __syncthreads();
        mma_chunk(acc, sb + 65536 + kc * 32768, sb + 196608);
    }
#pragma unroll
    for (int mt = 0; mt < 4; mt++)
#pragma unroll
        for (int half = 0; half < 2; half++) {
            const int gr = rowBase + warp_m * 64 + mt * 16 + r4 + half * 8;
#pragma unroll
            for (int nt = 0; nt < 4; nt++) {
                const int col = warp_n * 32 + nt * 8 + c2;
                float v0 = half ? acc[mt][nt].z : acc[mt][nt].x;
                float v1 = half ? acc[mt][nt].w : acc[mt][nt].y;
                const float2 sk = *(const float2*)(h2 + (size_t)gr * 128 + col);
                v0 += __ldg(bb2 + col) + sk.x;
                v1 += __ldg(bb2 + col + 1) + sk.y;
                *(float2*)(out + (size_t)gr * 128 + col) = make_float2(v0, v1);
            }
        }
}

// ---------------------------------------------------------------------------
extern "C" void kernel_launch(void* const* d_in, const int* in_sizes, int n_in,
                              void* d_out, int out_size)
{
    const float* x      = (const float*)d_in[0];
    const float* qkv_w  = (const float*)d_in[1];
    const float* qkv_b  = (const float*)d_in[2];
    const float* proj_w = (const float*)d_in[3];
    const float* proj_b = (const float*)d_in[4];
    const float* rpb    = (const float*)d_in[5];
    const float* g1     = (const float*)d_in[6];
    const float* b1     = (const float*)d_in[7];
    const float* g2     = (const float*)d_in[8];
    const float* b2     = (const float*)d_in[9];
    const float* w1     = (const float*)d_in[10];
    const float* bb1    = (const float*)d_in[11];
    const float* w2     = (const float*)d_in[12];
    const float* bb2    = (const float*)d_in[13];
    float* out = (float*)d_out;

    float *qkv, *h2;
    bf16 *wqh, *wql, *wph, *wpl, *w1h, *w1l, *w2h, *w2l;
    cudaGetSymbolAddress((void**)&qkv, g_qkv);
    cudaGetSymbolAddress((void**)&h2,  g_h2);
    cudaGetSymbolAddress((void**)&wqh, g_wqh);
    cudaGetSymbolAddress((void**)&wql, g_wql);
    cudaGetSymbolAddress((void**)&wph, g_wph);
    cudaGetSymbolAddress((void**)&wpl, g_wpl);
    cudaGetSymbolAddress((void**)&w1h, g_w1h);
    cudaGetSymbolAddress((void**)&w1l, g_w1l);
    cudaGetSymbolAddress((void**)&w2h, g_w2h);
    cudaGetSymbolAddress((void**)&w2l, g_w2l);

    cudaFuncSetAttribute(qkv_kernel,      cudaFuncAttributeMaxDynamicSharedMemorySize, 98304);
    cudaFuncSetAttribute(attnproj_kernel, cudaFuncAttributeMaxDynamicSharedMemorySize, 98304);
    cudaFuncSetAttribute(mlp_kernel,      cudaFuncAttributeMaxDynamicSharedMemorySize, 229376);

    // weight transpose+split (tiny)
    wconv<<<(384 * 128 + 255) / 256, 256>>>(qkv_w,  128, 384, wqh, wql);
    wconv<<<(128 * 128 + 255) / 256, 256>>>(proj_w, 128, 128, wph, wpl);
    wconv<<<(256 * 128 + 255) / 256, 256>>>(w1,     128, 256, w1h, w1l);
    wconv<<<(128 * 256 + 255) / 256, 256>>>(w2,     256, 128, w2h, w2l);

    qkv_kernel<<<TOK / 128, 256, 98304>>>(x, g1, b1, wqh, wql, qkv_b, qkv);
    attnproj_kernel<<<TOK / 128, 256, 98304>>>(qkv, rpb, wph, wpl, proj_b, x, h2);
    mlp_kernel<<<TOK / 128, 256, 229376>>>(h2, g2, b2, w1h, w1l, bb1,
                                           w2h, w2l, bb2, out);
}

// round 7
// speedup vs baseline: 1.6038x; 1.6038x over previous
#include <cuda_runtime.h>
#include <cuda_bf16.h>
#include <math.h>
#include <stdint.h>

// ---------------------------------------------------------------------------
// Swin block: B=32, H=W=128, C=128, WS=2, SS=1, NH=8, HD=16
// 3 fused kernels, all 96KB smem (2 CTA/SM), double-buffered k32 weight chunks.
// GEMMs: mma.sync bf16 hi/lo x3 (emulated fp32).
// ---------------------------------------------------------------------------

#define TOK   524288

typedef __nv_bfloat16 bf16;

__device__ float g_qkv[(size_t)TOK * 384];
__device__ float g_h2 [(size_t)TOK * 128];
__device__ bf16  g_wqh[384 * 128], g_wql[384 * 128];
__device__ bf16  g_wph[128 * 128], g_wpl[128 * 128];
__device__ bf16  g_w1h[256 * 128], g_w1l[256 * 128];
__device__ bf16  g_w2h[128 * 256], g_w2l[128 * 256];

// ---------------------------------------------------------------------------
__device__ __forceinline__ uint32_t smem_u32(const void* p) {
    uint32_t a;
    asm("{ .reg .u64 t; cvta.to.shared.u64 t, %1; cvt.u32.u64 %0, t; }"
        : "=r"(a) : "l"(p));
    return a;
}

#define SWZ128(o) ((o) ^ (((o) >> 3) & 0x70))
#define SWZ64(o)  ((o) ^ (((o) >> 3) & 0x30))

#define CP_ASYNC16(dst, src) \
    asm volatile("cp.async.cg.shared.global [%0], [%1], 16;" \
                 :: "r"(dst), "l"(src) : "memory")
#define CP_COMMIT()  asm volatile("cp.async.commit_group;" ::: "memory")
#define CP_WAIT0()   asm volatile("cp.async.wait_group 0;" ::: "memory")
#define CP_WAIT1()   asm volatile("cp.async.wait_group 1;" ::: "memory")

__device__ __forceinline__ void ldsm4(uint32_t r[4], uint32_t addr) {
    asm volatile("ldmatrix.sync.aligned.m8n8.x4.shared.b16 {%0,%1,%2,%3}, [%4];"
                 : "=r"(r[0]), "=r"(r[1]), "=r"(r[2]), "=r"(r[3]) : "r"(addr));
}

__device__ __forceinline__ void mma_bf16(float4& d, const uint32_t a[4],
                                         const uint32_t b[2]) {
    asm volatile(
        "mma.sync.aligned.m16n8k16.row.col.f32.bf16.bf16.f32 "
        "{%0,%1,%2,%3}, {%4,%5,%6,%7}, {%8,%9}, {%0,%1,%2,%3};"
        : "+f"(d.x), "+f"(d.y), "+f"(d.z), "+f"(d.w)
        : "r"(a[0]), "r"(a[1]), "r"(a[2]), "r"(a[3]), "r"(b[0]), "r"(b[1]));
}

__device__ __forceinline__ int orig_of(int r) {
    int win = r >> 2, s = r & 3;
    int b  = win >> 12;
    int w  = win & 4095;
    int wh = w >> 6, ww = w & 63;
    int ii = ((wh << 1) + (s >> 1) + 1) & 127;
    int jj = ((ww << 1) + (s & 1) + 1) & 127;
    return (b << 14) + (ii << 7) + jj;
}

__device__ __forceinline__ uint32_t pk2(float a, float b) {
    __nv_bfloat162 t = __floats2bfloat162_rn(a, b);
    return *(uint32_t*)&t;
}
__device__ __forceinline__ float bhi(float v) {
    return __bfloat162float(__float2bfloat16(v));
}

// ---------------------------------------------------------------------------
// LN of ROWS rows -> bf16 hi/lo SW128 operand region at smem offset 0.
// Region layout: 2 k64-chunks, chunk stride = ROWS*256 (hi ROWS*128 | lo).
// ---------------------------------------------------------------------------
template <bool GATHER, int ROWS>
__device__ __forceinline__ void ln_to_smem(
    const float* __restrict__ in, const float* __restrict__ gamma,
    const float* __restrict__ beta, char* smem, int rowBase)
{
    const int tid = threadIdx.x, lane = tid & 31, wid = tid >> 5;
    const float4 g = *(const float4*)(gamma + lane * 4);
    const float4 b = *(const float4*)(beta  + lane * 4);
    const uint32_t colOff = (uint32_t)((lane & 15) * 8);
    char* dhi = smem + (lane >> 4) * (ROWS * 256);
#pragma unroll 4
    for (int r = wid; r < ROWS; r += 8) {
        int src = GATHER ? orig_of(rowBase + r) : (rowBase + r);
        float4 v = __ldg((const float4*)(in + (size_t)src * 128 + lane * 4));
        float s = v.x + v.y + v.z + v.w;
        float q = v.x * v.x + v.y * v.y + v.z * v.z + v.w * v.w;
#pragma unroll
        for (int o = 16; o; o >>= 1) {
            s += __shfl_xor_sync(0xffffffffu, s, o);
            q += __shfl_xor_sync(0xffffffffu, q, o);
        }
        float mean = s * (1.0f / 128.0f);
        float rstd = rsqrtf(q * (1.0f / 128.0f) - mean * mean + 1e-5f);
        float o0 = (v.x - mean) * rstd * g.x + b.x;
        float o1 = (v.y - mean) * rstd * g.y + b.y;
        float o2 = (v.z - mean) * rstd * g.z + b.z;
        float o3 = (v.w - mean) * rstd * g.w + b.w;
        float h0 = bhi(o0), h1 = bhi(o1), h2 = bhi(o2), h3 = bhi(o3);
        uint32_t o16 = SWZ128((uint32_t)(r * 128) + colOff);
        *(uint2*)(dhi + o16)              = make_uint2(pk2(h0, h1), pk2(h2, h3));
        *(uint2*)(dhi + ROWS * 128 + o16) = make_uint2(pk2(o0 - h0, o1 - h1),
                                                       pk2(o2 - h2, o3 - h3));
    }
}

// ---------------------------------------------------------------------------
// cp.async one 128(N) x 32(k) bf16 hi/lo weight chunk -> 16KB SW64 region.
// ---------------------------------------------------------------------------
__device__ __forceinline__ void load_w16(
    uint32_t dst, const bf16* __restrict__ hi, const bf16* __restrict__ lo,
    int rowOff, int kOff, int kStride)
{
    const int tid = threadIdx.x, c16 = tid & 3;
#pragma unroll
    for (int it = 0; it < 2; it++) {
        int row = (tid >> 2) + it * 64;
        uint32_t d = dst + SWZ64((uint32_t)(row * 64 + c16 * 16));
        const size_t s = (size_t)(rowOff + row) * kStride + kOff + c16 * 8;
        CP_ASYNC16(d, hi + s);
        CP_ASYNC16(d + 8192, lo + s);
    }
    CP_COMMIT();
}

// ---------------------------------------------------------------------------
// k32 half-chunk warp MMA. A: SW128 k64-chunk at aBase (hi | lo at +HLA),
// khalf selects k 0-31 / 32-63.  B: SW64 16KB W chunk (hi 8KB | lo 8KB).
// ---------------------------------------------------------------------------
template <int MT, int HLA>
__device__ __forceinline__ void mma_half(
    float4 (&acc)[MT][4], uint32_t aBase, int khalf, uint32_t bBase)
{
    const int lane = threadIdx.x & 31, wid = threadIdx.x >> 5;
    const int warp_m = wid >> 2, warp_n = wid & 3;
    const int arow = warp_m * (MT * 16) + (lane & 15);
    const int akb  = (lane >> 4) * 8;
    const int brow = warp_n * 32 + ((lane >> 4) & 1) * 8 + (lane & 7);
    const int bkb  = ((lane >> 3) & 1) * 8;
#pragma unroll
    for (int ks = 0; ks < 2; ks++) {
        const int kA = (khalf * 32 + ks * 16 + akb) * 2;
        const int kB = (ks * 16 + bkb) * 2;
        uint32_t bh[2][4], bl[2][4];
#pragma unroll
        for (int i = 0; i < 2; i++) {
            uint32_t boff = SWZ64((uint32_t)((brow + i * 16) * 64 + kB));
            ldsm4(bh[i], bBase + boff);
            ldsm4(bl[i], bBase + 8192 + boff);
        }
#pragma unroll
        for (int mt = 0; mt < MT; mt++) {
            uint32_t aoff = SWZ128((uint32_t)((arow + mt * 16) * 128 + kA));
            uint32_t ah[4], al[4];
            ldsm4(ah, aBase + aoff);
            ldsm4(al, aBase + HLA + aoff);
#pragma unroll
            for (int nt = 0; nt < 4; nt++) {
                mma_bf16(acc[mt][nt], ah, &bh[nt >> 1][(nt & 1) * 2]);
                mma_bf16(acc[mt][nt], ah, &bl[nt >> 1][(nt & 1) * 2]);
                mma_bf16(acc[mt][nt], al, &bh[nt >> 1][(nt & 1) * 2]);
            }
        }
    }
}

// ---------------------------------------------------------------------------
// Weight transpose + split (all 4 weights, one launch)
// ---------------------------------------------------------------------------
__global__ void wconv_all(
    const float* __restrict__ qkv_w, const float* __restrict__ proj_w,
    const float* __restrict__ w1, const float* __restrict__ w2,
    bf16* wqh, bf16* wql, bf16* wph, bf16* wpl,
    bf16* w1h, bf16* w1l, bf16* w2h, bf16* w2l)
{
    int idx = blockIdx.x * 256 + threadIdx.x;   // 131072 total
    const float* w; bf16 *hi, *lo; int K, N;
    if (idx < 49152)       { w = qkv_w;  hi = wqh; lo = wql; K = 128; N = 384; }
    else if (idx < 65536)  { idx -= 49152; w = proj_w; hi = wph; lo = wpl; K = 128; N = 128; }
    else if (idx < 98304)  { idx -= 65536; w = w1; hi = w1h; lo = w1l; K = 128; N = 256; }
    else                   { idx -= 98304; w = w2; hi = w2h; lo = w2l; K = 256; N = 128; }
    int n = idx / K, k = idx - n * K;
    float v = w[(size_t)k * N + n];
    float h = bhi(v);
    hi[idx] = __float2bfloat16(v);
    lo[idx] = __float2bfloat16(v - h);
}

// ---------------------------------------------------------------------------
// Kernel 1: LN1(+gather) + qkv GEMM.  A 64KB @0 | W 2x16KB @65536 -> 96KB
// 12 k32 chunks (3 passes x 4), double-buffered.
// ---------------------------------------------------------------------------
__global__ __launch_bounds__(256, 2) void qkv_kernel(
    const float* __restrict__ x, const float* __restrict__ g1,
    const float* __restrict__ b1,
    const bf16* __restrict__ wqh, const bf16* __restrict__ wql,
    const float* __restrict__ qkv_b, float* __restrict__ qkv)
{
    extern __shared__ char smem[];
    const uint32_t sb = smem_u32(smem);
    const int tid = threadIdx.x, lane = tid & 31, wid = tid >> 5;
    const int warp_m = wid >> 2, warp_n = wid & 3;
    const int rowBase = blockIdx.x << 7;
    const int r4 = lane >> 2, c2 = (lane & 3) * 2;

    auto issueW = [&](int c) {
        load_w16(sb + 65536 + (c & 1) * 16384, wqh, wql,
                 (c >> 2) * 128, (c & 3) * 32, 128);
    };

    issueW(0);
    ln_to_smem<true, 128>(x, g1, b1, smem, rowBase);
    __syncthreads();
    issueW(1);

#pragma unroll
    for (int p = 0; p < 3; p++) {
        float4 acc[4][4];
#pragma unroll
        for (int i = 0; i < 4; i++)
#pragma unroll
            for (int j = 0; j < 4; j++) acc[i][j] = make_float4(0, 0, 0, 0);
#pragma unroll
        for (int h = 0; h < 4; h++) {
            const int c = p * 4 + h;
            if (c == 11) CP_WAIT0(); else CP_WAIT1();
            __syncthreads();
            mma_half<4, 16384>(acc, sb + (h >> 1) * 32768, h & 1,
                               sb + 65536 + (c & 1) * 16384);
            __syncthreads();
            if (c + 2 <= 11) issueW(c + 2);
        }
        const float scale = (p == 0) ? 0.25f : 1.0f;
#pragma unroll
        for (int mt = 0; mt < 4; mt++)
#pragma unroll
            for (int half = 0; half < 2; half++) {
                const int gr = rowBase + warp_m * 64 + mt * 16 + r4 + half * 8;
#pragma unroll
                for (int nt = 0; nt < 4; nt++) {
                    const int col = p * 128 + warp_n * 32 + nt * 8 + c2;
                    float v0 = half ? acc[mt][nt].z : acc[mt][nt].x;
                    float v1 = half ? acc[mt][nt].w : acc[mt][nt].y;
                    v0 = (v0 + __ldg(qkv_b + col)) * scale;
                    v1 = (v1 + __ldg(qkv_b + col + 1)) * scale;
                    *(float2*)(qkv + (size_t)gr * 384 + col) = make_float2(v0, v1);
                }
            }
    }
}

// ---------------------------------------------------------------------------
// Kernel 2: window attention + proj GEMM + residual scatter.
// O 64KB @0 | W 2x16KB @65536 -> 96KB.  4 k32 chunks.
// ---------------------------------------------------------------------------
__global__ __launch_bounds__(256, 2) void attnproj_kernel(
    const float* __restrict__ qkv, const float* __restrict__ rpb,
    const bf16* __restrict__ wph, const bf16* __restrict__ wpl,
    const float* __restrict__ proj_b, const float* __restrict__ x,
    float* __restrict__ h2)
{
    extern __shared__ char smem[];
    const uint32_t sb = smem_u32(smem);
    const int tid = threadIdx.x, lane = tid & 31, wid = tid >> 5;
    const int warp_m = wid >> 2, warp_n = wid & 3;
    const int rowBase = blockIdx.x << 7;
    const int win0    = blockIdx.x << 5;
    const int h = lane >> 2, i = lane & 3;
    const int dy1 = i >> 1, dx1 = i & 1;

    auto issueW = [&](int c) {
        load_w16(sb + 65536 + (c & 1) * 16384, wph, wpl, 0, (c & 3) * 32, 128);
    };
    issueW(0);

    // ---- attention: each warp handles 4 windows ----------------------------
#pragma unroll
    for (int t = 0; t < 4; t++) {
        const int wl  = wid * 4 + t;
        const int win = win0 + wl;
        const int w   = win & 4095;
        const bool mr = ((w >> 6) == 63);
        const bool mc = ((w & 63) == 63);
        const float* base = qkv + (size_t)win * (4 * 384);

        float q[16];
        const float* qp = base + i * 384 + h * 16;
#pragma unroll
        for (int d4 = 0; d4 < 4; d4++) {
            float4 v = __ldg((const float4*)(qp + d4 * 4));
            q[d4 * 4 + 0] = v.x; q[d4 * 4 + 1] = v.y;
            q[d4 * 4 + 2] = v.z; q[d4 * 4 + 3] = v.w;
        }
        float s[4];
#pragma unroll
        for (int j = 0; j < 4; j++) {
            const float* kp = base + j * 384 + 128 + h * 16;
            float a = 0.0f;
#pragma unroll
            for (int d4 = 0; d4 < 4; d4++) {
                float4 v = __ldg((const float4*)(kp + d4 * 4));
                a += q[d4 * 4 + 0] * v.x + q[d4 * 4 + 1] * v.y
                   + q[d4 * 4 + 2] * v.z + q[d4 * 4 + 3] * v.w;
            }
            int dy2 = j >> 1, dx2 = j & 1;
            bool ok = (!mr || dy1 == dy2) && (!mc || dx1 == dx2);
            s[j] = a + __ldg(rpb + ((dy1 - dy2 + 1) * 3 + (dx1 - dx2 + 1)) * 8 + h)
                 + (ok ? 0.0f : -100.0f);
        }
        float mx = fmaxf(fmaxf(s[0], s[1]), fmaxf(s[2], s[3]));
        float p[4], sum = 0.0f;
#pragma unroll
        for (int j = 0; j < 4; j++) { p[j] = expf(s[j] - mx); sum += p[j]; }
        float inv = 1.0f / sum;

        float ov[16];
#pragma unroll
        for (int d = 0; d < 16; d++) ov[d] = 0.0f;
#pragma unroll
        for (int j = 0; j < 4; j++) {
            const float* vp = base + j * 384 + 256 + h * 16;
            float pj = p[j] * inv;
#pragma unroll
            for (int d4 = 0; d4 < 4; d4++) {
                float4 v = __ldg((const float4*)(vp + d4 * 4));
                ov[d4 * 4 + 0] += pj * v.x; ov[d4 * 4 + 1] += pj * v.y;
                ov[d4 * 4 + 2] += pj * v.z; ov[d4 * 4 + 3] += pj * v.w;
            }
        }
        const int row = wl * 4 + i;
#pragma unroll
        for (int d4 = 0; d4 < 4; d4++) {
            const int ch = h * 16 + d4 * 4;
            char* dst = smem + (ch >> 6) * 32768;
            uint32_t o16 = SWZ128((uint32_t)(row * 128 + (ch & 63) * 2));
            float a0 = ov[d4 * 4], a1 = ov[d4 * 4 + 1],
                  a2 = ov[d4 * 4 + 2], a3 = ov[d4 * 4 + 3];
            float h0 = bhi(a0), h1 = bhi(a1), h2v = bhi(a2), h3 = bhi(a3);
            *(uint2*)(dst + o16)         = make_uint2(pk2(h0, h1), pk2(h2v, h3));
            *(uint2*)(dst + 16384 + o16) = make_uint2(pk2(a0 - h0, a1 - h1),
                                                      pk2(a2 - h2v, a3 - h3));
        }
    }
    __syncthreads();
    issueW(1);

    // ---- proj GEMM ----------------------------------------------------------
    float4 acc[4][4];
#pragma unroll
    for (int a = 0; a < 4; a++)
#pragma unroll
        for (int j = 0; j < 4; j++) acc[a][j] = make_float4(0, 0, 0, 0);
#pragma unroll
    for (int hh = 0; hh < 4; hh++) {
        if (hh == 3) CP_WAIT0(); else CP_WAIT1();
        __syncthreads();
        mma_half<4, 16384>(acc, sb + (hh >> 1) * 32768, hh & 1,
                           sb + 65536 + (hh & 1) * 16384);
        __syncthreads();
        if (hh + 2 <= 3) issueW(hh + 2);
    }

    const int r4 = lane >> 2, c2 = (lane & 3) * 2;
#pragma unroll
    for (int mt = 0; mt < 4; mt++)
#pragma unroll
        for (int half = 0; half < 2; half++) {
            const int gr = rowBase + warp_m * 64 + mt * 16 + r4 + half * 8;
            const size_t outRow = (size_t)orig_of(gr);
#pragma unroll
            for (int nt = 0; nt < 4; nt++) {
                const int col = warp_n * 32 + nt * 8 + c2;
                float v0 = half ? acc[mt][nt].z : acc[mt][nt].x;
                float v1 = half ? acc[mt][nt].w : acc[mt][nt].y;
                const float2 sk = *(const float2*)(x + outRow * 128 + col);
                v0 += __ldg(proj_b + col) + sk.x;
                v1 += __ldg(proj_b + col + 1) + sk.y;
                *(float2*)(h2 + outRow * 128 + col) = make_float2(v0, v1);
            }
        }
}

// ---------------------------------------------------------------------------
// Kernel 3: LN2 + MLP1(GELU) + MLP2 + residual, M=64 tiles, interleaved.
// L2A 32KB @0 | M1 32KB @32768 | W 2x16KB @65536 -> 96KB.  16 k32 chunks.
// seg0: W1 pass0 -> gelu -> M1;  seg1: W2 k0-127 (acc2);
// seg2: W1 pass1 -> gelu -> M1;  seg3: W2 k128-255 (acc2);  epilogue.
// ---------------------------------------------------------------------------
__global__ __launch_bounds__(256, 2) void mlp_kernel(
    const float* __restrict__ h2, const float* __restrict__ g2,
    const float* __restrict__ b2,
    const bf16* __restrict__ w1h, const bf16* __restrict__ w1l,
    const float* __restrict__ bb1,
    const bf16* __restrict__ w2h, const bf16* __restrict__ w2l,
    const float* __restrict__ bb2, float* __restrict__ out)
{
    extern __shared__ char smem[];
    const uint32_t sb = smem_u32(smem);
    const int tid = threadIdx.x, lane = tid & 31, wid = tid >> 5;
    const int warp_m = wid >> 2, warp_n = wid & 3;
    const int rowBase = blockIdx.x << 6;   // 64 rows per CTA
    const int r4 = lane >> 2, c2 = (lane & 3) * 2;

    auto issueW = [&](int c) {
        const int seg = c >> 2, sub = c & 3;
        const uint32_t dst = sb + 65536 + (c & 1) * 16384;
        if (seg == 0)      load_w16(dst, w1h, w1l, 0,   sub * 32, 128);
        else if (seg == 1) load_w16(dst, w2h, w2l, 0,   sub * 32, 256);
        else if (seg == 2) load_w16(dst, w1h, w1l, 128, sub * 32, 128);
        else               load_w16(dst, w2h, w2l, 0, 128 + sub * 32, 256);
    };

    issueW(0);
    ln_to_smem<false, 64>(h2, g2, b2, smem, rowBase);
    __syncthreads();
    issueW(1);

    float4 acc2[2][4];
#pragma unroll
    for (int a = 0; a < 2; a++)
#pragma unroll
        for (int j = 0; j < 4; j++) acc2[a][j] = make_float4(0, 0, 0, 0);

#pragma unroll
    for (int seg = 0; seg < 4; seg++) {
        const bool isM1 = (seg & 1) == 0;       // mlp1 segments: 0, 2
        float4 acc1[2][4];
        if (isM1) {
#pragma unroll
            for (int a = 0; a < 2; a++)
#pragma unroll
                for (int j = 0; j < 4; j++) acc1[a][j] = make_float4(0, 0, 0, 0);
        }
        const uint32_t aB = isM1 ? sb : sb + 32768;
#pragma unroll
        for (int hh = 0; hh < 4; hh++) {
            const int c = seg * 4 + hh;
            if (c == 15) CP_WAIT0(); else CP_WAIT1();
            __syncthreads();
            mma_half<2, 8192>(isM1 ? acc1 : acc2, aB + (hh >> 1) * 16384,
                              hh & 1, sb + 65536 + (c & 1) * 16384);
            __syncthreads();
            if (c + 2 <= 15) issueW(c + 2);
        }
        if (isM1) {
            // gelu -> M1 (k indices = local cols 0..127 of this pass)
            const int bOff = (seg == 0) ? 0 : 128;
#pragma unroll
            for (int mt = 0; mt < 2; mt++)
#pragma unroll
                for (int half = 0; half < 2; half++) {
                    const int row = warp_m * 32 + mt * 16 + r4 + half * 8;
#pragma unroll
                    for (int nt = 0; nt < 4; nt++) {
                        const int ch = warp_n * 32 + nt * 8 + c2;
                        float v0 = half ? acc1[mt][nt].z : acc1[mt][nt].x;
                        float v1 = half ? acc1[mt][nt].w : acc1[mt][nt].y;
                        v0 += __ldg(bb1 + bOff + ch);
                        v1 += __ldg(bb1 + bOff + ch + 1);
                        v0 = v0 * normcdff(v0);
                        v1 = v1 * normcdff(v1);
                        float h0 = bhi(v0), h1 = bhi(v1);
                        char* dst = smem + 32768 + (ch >> 6) * 16384;
                        uint32_t o16 = SWZ128((uint32_t)(row * 128 + (ch & 63) * 2));
                        *(uint32_t*)(dst + o16)        = pk2(h0, h1);
                        *(uint32_t*)(dst + 8192 + o16) = pk2(v0 - h0, v1 - h1);
                    }
                }
            // visibility to all warps ensured by the wait+sync at next seg start
        }
    }

    // ---- final epilogue: out = acc2 + b2 + h2 -------------------------------
#pragma unroll
    for (int mt = 0; mt < 2; mt++)
#pragma unroll
        for (int half = 0; half < 2; half++) {
            const int gr = rowBase + warp_m * 32 + mt * 16 + r4 + half * 8;
#pragma unroll
            for (int nt = 0; nt < 4; nt++) {
                const int col = warp_n * 32 + nt * 8 + c2;
                float v0 = half ? acc2[mt][nt].z : acc2[mt][nt].x;
                float v1 = half ? acc2[mt][nt].w : acc2[mt][nt].y;
                const float2 sk = *(const float2*)(h2 + (size_t)gr * 128 + col);
                v0 += __ldg(bb2 + col) + sk.x;
                v1 += __ldg(bb2 + col + 1) + sk.y;
                *(float2*)(out + (size_t)gr * 128 + col) = make_float2(v0, v1);
            }
        }
}

// ---------------------------------------------------------------------------
extern "C" void kernel_launch(void* const* d_in, const int* in_sizes, int n_in,
                              void* d_out, int out_size)
{
    const float* x      = (const float*)d_in[0];
    const float* qkv_w  = (const float*)d_in[1];
    const float* qkv_b  = (const float*)d_in[2];
    const float* proj_w = (const float*)d_in[3];
    const float* proj_b = (const float*)d_in[4];
    const float* rpb    = (const float*)d_in[5];
    const float* g1     = (const float*)d_in[6];
    const float* b1     = (const float*)d_in[7];
    const float* g2     = (const float*)d_in[8];
    const float* b2     = (const float*)d_in[9];
    const float* w1     = (const float*)d_in[10];
    const float* bb1    = (const float*)d_in[11];
    const float* w2     = (const float*)d_in[12];
    const float* bb2    = (const float*)d_in[13];
    float* out = (float*)d_out;

    float *qkv, *h2;
    bf16 *wqh, *wql, *wph, *wpl, *w1h, *w1l, *w2h, *w2l;
    cudaGetSymbolAddress((void**)&qkv, g_qkv);
    cudaGetSymbolAddress((void**)&h2,  g_h2);
    cudaGetSymbolAddress((void**)&wqh, g_wqh);
    cudaGetSymbolAddress((void**)&wql, g_wql);
    cudaGetSymbolAddress((void**)&wph, g_wph);
    cudaGetSymbolAddress((void**)&wpl, g_wpl);
    cudaGetSymbolAddress((void**)&w1h, g_w1h);
    cudaGetSymbolAddress((void**)&w1l, g_w1l);
    cudaGetSymbolAddress((void**)&w2h, g_w2h);
    cudaGetSymbolAddress((void**)&w2l, g_w2l);

    cudaFuncSetAttribute(qkv_kernel,      cudaFuncAttributeMaxDynamicSharedMemorySize, 98304);
    cudaFuncSetAttribute(attnproj_kernel, cudaFuncAttributeMaxDynamicSharedMemorySize, 98304);
    cudaFuncSetAttribute(mlp_kernel,      cudaFuncAttributeMaxDynamicSharedMemorySize, 98304);

    wconv_all<<<512, 256>>>(qkv_w, proj_w, w1, w2,
                            wqh, wql, wph, wpl, w1h, w1l, w2h, w2l);

    qkv_kernel<<<TOK / 128, 256, 98304>>>(x, g1, b1, wqh, wql, qkv_b, qkv);
    attnproj_kernel<<<TOK / 128, 256, 98304>>>(qkv, rpb, wph, wpl, proj_b, x, h2);
    mlp_kernel<<<TOK / 64, 256, 98304>>>(h2, g2, b2, w1h, w1l, bb1,
                                         w2h, w2l, bb2, out);
}

// round 8
// speedup vs baseline: 1.6794x; 1.0471x over previous
#include <cuda_runtime.h>
#include <cuda_bf16.h>
#include <math.h>
#include <stdint.h>

// ---------------------------------------------------------------------------
// Swin block: B=32, H=W=128, C=128, WS=2, SS=1, NH=8, HD=16
// 3 fused kernels, 112KB smem (2 CTA/SM), 3-stage weight pipeline,
// one barrier per k32 chunk.  qkv intermediate stored bf16.
// GEMMs: mma.sync bf16 hi/lo x3 (emulated fp32).
// ---------------------------------------------------------------------------

#define TOK   524288

typedef __nv_bfloat16 bf16;

__device__ bf16  g_qkv[(size_t)TOK * 384];   // bf16 qkv (q pre-scaled)
__device__ float g_h2 [(size_t)TOK * 128];
__device__ bf16  g_wqh[384 * 128], g_wql[384 * 128];
__device__ bf16  g_wph[128 * 128], g_wpl[128 * 128];
__device__ bf16  g_w1h[256 * 128], g_w1l[256 * 128];
__device__ bf16  g_w2h[128 * 256], g_w2l[128 * 256];

// ---------------------------------------------------------------------------
__device__ __forceinline__ uint32_t smem_u32(const void* p) {
    uint32_t a;
    asm("{ .reg .u64 t; cvta.to.shared.u64 t, %1; cvt.u32.u64 %0, t; }"
        : "=r"(a) : "l"(p));
    return a;
}

#define SWZ128(o) ((o) ^ (((o) >> 3) & 0x70))
#define SWZ64(o)  ((o) ^ (((o) >> 3) & 0x30))

#define CP_ASYNC16(dst, src) \
    asm volatile("cp.async.cg.shared.global [%0], [%1], 16;" \
                 :: "r"(dst), "l"(src) : "memory")
#define CP_COMMIT()  asm volatile("cp.async.commit_group;" ::: "memory")
#define CP_WAIT0()   asm volatile("cp.async.wait_group 0;" ::: "memory")
#define CP_WAIT1()   asm volatile("cp.async.wait_group 1;" ::: "memory")

__device__ __forceinline__ void ldsm4(uint32_t r[4], uint32_t addr) {
    asm volatile("ldmatrix.sync.aligned.m8n8.x4.shared.b16 {%0,%1,%2,%3}, [%4];"
                 : "=r"(r[0]), "=r"(r[1]), "=r"(r[2]), "=r"(r[3]) : "r"(addr));
}

__device__ __forceinline__ void mma_bf16(float4& d, const uint32_t a[4],
                                         const uint32_t b[2]) {
    asm volatile(
        "mma.sync.aligned.m16n8k16.row.col.f32.bf16.bf16.f32 "
        "{%0,%1,%2,%3}, {%4,%5,%6,%7}, {%8,%9}, {%0,%1,%2,%3};"
        : "+f"(d.x), "+f"(d.y), "+f"(d.z), "+f"(d.w)
        : "r"(a[0]), "r"(a[1]), "r"(a[2]), "r"(a[3]), "r"(b[0]), "r"(b[1]));
}

__device__ __forceinline__ int orig_of(int r) {
    int win = r >> 2, s = r & 3;
    int b  = win >> 12;
    int w  = win & 4095;
    int wh = w >> 6, ww = w & 63;
    int ii = ((wh << 1) + (s >> 1) + 1) & 127;
    int jj = ((ww << 1) + (s & 1) + 1) & 127;
    return (b << 14) + (ii << 7) + jj;
}

__device__ __forceinline__ uint32_t pk2(float a, float b) {
    __nv_bfloat162 t = __floats2bfloat162_rn(a, b);
    return *(uint32_t*)&t;
}
__device__ __forceinline__ float bhi(float v) {
    return __bfloat162float(__float2bfloat16(v));
}
// load 4 consecutive bf16 -> float4
__device__ __forceinline__ float4 ld4bf(const bf16* p) {
    uint2 u = __ldg((const uint2*)p);
    float2 fa = __bfloat1622float2(*(__nv_bfloat162*)&u.x);
    float2 fb = __bfloat1622float2(*(__nv_bfloat162*)&u.y);
    return make_float4(fa.x, fa.y, fb.x, fb.y);
}

// ---------------------------------------------------------------------------
// LN of ROWS rows -> bf16 hi/lo SW128 operand region at smem offset 0.
// ---------------------------------------------------------------------------
template <bool GATHER, int ROWS>
__device__ __forceinline__ void ln_to_smem(
    const float* __restrict__ in, const float* __restrict__ gamma,
    const float* __restrict__ beta, char* smem, int rowBase)
{
    const int tid = threadIdx.x, lane = tid & 31, wid = tid >> 5;
    const float4 g = *(const float4*)(gamma + lane * 4);
    const float4 b = *(const float4*)(beta  + lane * 4);
    const uint32_t colOff = (uint32_t)((lane & 15) * 8);
    char* dhi = smem + (lane >> 4) * (ROWS * 256);
#pragma unroll 4
    for (int r = wid; r < ROWS; r += 8) {
        int src = GATHER ? orig_of(rowBase + r) : (rowBase + r);
        float4 v = __ldg((const float4*)(in + (size_t)src * 128 + lane * 4));
        float s = v.x + v.y + v.z + v.w;
        float q = v.x * v.x + v.y * v.y + v.z * v.z + v.w * v.w;
#pragma unroll
        for (int o = 16; o; o >>= 1) {
            s += __shfl_xor_sync(0xffffffffu, s, o);
            q += __shfl_xor_sync(0xffffffffu, q, o);
        }
        float mean = s * (1.0f / 128.0f);
        float rstd = rsqrtf(q * (1.0f / 128.0f) - mean * mean + 1e-5f);
        float o0 = (v.x - mean) * rstd * g.x + b.x;
        float o1 = (v.y - mean) * rstd * g.y + b.y;
        float o2 = (v.z - mean) * rstd * g.z + b.z;
        float o3 = (v.w - mean) * rstd * g.w + b.w;
        float h0 = bhi(o0), h1 = bhi(o1), h2 = bhi(o2), h3 = bhi(o3);
        uint32_t o16 = SWZ128((uint32_t)(r * 128) + colOff);
        *(uint2*)(dhi + o16)              = make_uint2(pk2(h0, h1), pk2(h2, h3));
        *(uint2*)(dhi + ROWS * 128 + o16) = make_uint2(pk2(o0 - h0, o1 - h1),
                                                       pk2(o2 - h2, o3 - h3));
    }
}

// ---------------------------------------------------------------------------
// cp.async one 128(N) x 32(k) bf16 hi/lo weight chunk -> 16KB SW64 region.
// ---------------------------------------------------------------------------
__device__ __forceinline__ void load_w16(
    uint32_t dst, const bf16* __restrict__ hi, const bf16* __restrict__ lo,
    int rowOff, int kOff, int kStride)
{
    const int tid = threadIdx.x, c16 = tid & 3;
#pragma unroll
    for (int it = 0; it < 2; it++) {
        int row = (tid >> 2) + it * 64;
        uint32_t d = dst + SWZ64((uint32_t)(row * 64 + c16 * 16));
        const size_t s = (size_t)(rowOff + row) * kStride + kOff + c16 * 8;
        CP_ASYNC16(d, hi + s);
        CP_ASYNC16(d + 8192, lo + s);
    }
    CP_COMMIT();
}

// ---------------------------------------------------------------------------
// k32 half-chunk warp MMA (A SW128, hi|lo at +HLA; B 16KB SW64 hi|lo).
// ---------------------------------------------------------------------------
template <int MT, int HLA>
__device__ __forceinline__ void mma_half(
    float4 (&acc)[MT][4], uint32_t aBase, int khalf, uint32_t bBase)
{
    const int lane = threadIdx.x & 31, wid = threadIdx.x >> 5;
    const int warp_m = wid >> 2, warp_n = wid & 3;
    const int arow = warp_m * (MT * 16) + (lane & 15);
    const int akb  = (lane >> 4) * 8;
    const int brow = warp_n * 32 + ((lane >> 4) & 1) * 8 + (lane & 7);
    const int bkb  = ((lane >> 3) & 1) * 8;
#pragma unroll
    for (int ks = 0; ks < 2; ks++) {
        const int kA = (khalf * 32 + ks * 16 + akb) * 2;
        const int kB = (ks * 16 + bkb) * 2;
        uint32_t bh[2][4], bl[2][4];
#pragma unroll
        for (int i = 0; i < 2; i++) {
            uint32_t boff = SWZ64((uint32_t)((brow + i * 16) * 64 + kB));
            ldsm4(bh[i], bBase + boff);
            ldsm4(bl[i], bBase + 8192 + boff);
        }
#pragma unroll
        for (int mt = 0; mt < MT; mt++) {
            uint32_t aoff = SWZ128((uint32_t)((arow + mt * 16) * 128 + kA));
            uint32_t ah[4], al[4];
            ldsm4(ah, aBase + aoff);
            ldsm4(al, aBase + HLA + aoff);
#pragma unroll
            for (int nt = 0; nt < 4; nt++) {
                mma_bf16(acc[mt][nt], ah, &bh[nt >> 1][(nt & 1) * 2]);
                mma_bf16(acc[mt][nt], ah, &bl[nt >> 1][(nt & 1) * 2]);
                mma_bf16(acc[mt][nt], al, &bh[nt >> 1][(nt & 1) * 2]);
            }
        }
    }
}

// ---------------------------------------------------------------------------
// Weight transpose + split (all 4 weights, one launch)
// ---------------------------------------------------------------------------
__global__ void wconv_all(
    const float* __restrict__ qkv_w, const float* __restrict__ proj_w,
    const float* __restrict__ w1, const float* __restrict__ w2,
    bf16* wqh, bf16* wql, bf16* wph, bf16* wpl,
    bf16* w1h, bf16* w1l, bf16* w2h, bf16* w2l)
{
    int idx = blockIdx.x * 256 + threadIdx.x;   // 131072 total
    const float* w; bf16 *hi, *lo; int K, N;
    if (idx < 49152)       { w = qkv_w;  hi = wqh; lo = wql; K = 128; N = 384; }
    else if (idx < 65536)  { idx -= 49152; w = proj_w; hi = wph; lo = wpl; K = 128; N = 128; }
    else if (idx < 98304)  { idx -= 65536; w = w1; hi = w1h; lo = w1l; K = 128; N = 256; }
    else                   { idx -= 98304; w = w2; hi = w2h; lo = w2l; K = 256; N = 128; }
    int n = idx / K, k = idx - n * K;
    float v = w[(size_t)k * N + n];
    float h = bhi(v);
    hi[idx] = __float2bfloat16(v);
    lo[idx] = __float2bfloat16(v - h);
}

// ---------------------------------------------------------------------------
// Kernel 1: LN1(+gather) + qkv GEMM -> bf16 qkv.
// A 64KB @0 | W 3x16KB @65536 -> 112KB.  12 k32 chunks, 3-stage.
// ---------------------------------------------------------------------------
__global__ __launch_bounds__(256, 2) void qkv_kernel(
    const float* __restrict__ x, const float* __restrict__ g1,
    const float* __restrict__ b1,
    const bf16* __restrict__ wqh, const bf16* __restrict__ wql,
    const float* __restrict__ qkv_b, bf16* __restrict__ qkv)
{
    extern __shared__ char smem[];
    const uint32_t sb = smem_u32(smem);
    const int tid = threadIdx.x, lane = tid & 31, wid = tid >> 5;
    const int warp_m = wid >> 2, warp_n = wid & 3;
    const int rowBase = blockIdx.x << 7;
    const int r4 = lane >> 2, c2 = (lane & 3) * 2;

    auto issueW = [&](int c) {
        load_w16(sb + 65536 + (c % 3) * 16384, wqh, wql,
                 (c >> 2) * 128, (c & 3) * 32, 128);
    };

    issueW(0);
    ln_to_smem<true, 128>(x, g1, b1, smem, rowBase);
    issueW(1);

#pragma unroll
    for (int p = 0; p < 3; p++) {
        float4 acc[4][4];
#pragma unroll
        for (int i = 0; i < 4; i++)
#pragma unroll
            for (int j = 0; j < 4; j++) acc[i][j] = make_float4(0, 0, 0, 0);
#pragma unroll
        for (int h = 0; h < 4; h++) {
            const int c = p * 4 + h;
            if (c == 11) CP_WAIT0(); else CP_WAIT1();
            __syncthreads();
            mma_half<4, 16384>(acc, sb + (h >> 1) * 32768, h & 1,
                               sb + 65536 + (c % 3) * 16384);
            if (c + 2 <= 11) issueW(c + 2);
        }
        const float scale = (p == 0) ? 0.25f : 1.0f;
#pragma unroll
        for (int mt = 0; mt < 4; mt++)
#pragma unroll
            for (int half = 0; half < 2; half++) {
                const int gr = rowBase + warp_m * 64 + mt * 16 + r4 + half * 8;
#pragma unroll
                for (int nt = 0; nt < 4; nt++) {
                    const int col = p * 128 + warp_n * 32 + nt * 8 + c2;
                    float v0 = half ? acc[mt][nt].z : acc[mt][nt].x;
                    float v1 = half ? acc[mt][nt].w : acc[mt][nt].y;
                    v0 = (v0 + __ldg(qkv_b + col)) * scale;
                    v1 = (v1 + __ldg(qkv_b + col + 1)) * scale;
                    *(uint32_t*)(qkv + (size_t)gr * 384 + col) = pk2(v0, v1);
                }
            }
    }
}

// ---------------------------------------------------------------------------
// Kernel 2: window attention (bf16 qkv) + proj GEMM + residual scatter.
// O 64KB @0 | W 3x16KB @65536 -> 112KB.  4 k32 chunks, 3-stage.
// ---------------------------------------------------------------------------
__global__ __launch_bounds__(256, 2) void attnproj_kernel(
    const bf16* __restrict__ qkv, const float* __restrict__ rpb,
    const bf16* __restrict__ wph, const bf16* __restrict__ wpl,
    const float* __restrict__ proj_b, const float* __restrict__ x,
    float* __restrict__ h2)
{
    extern __shared__ char smem[];
    const uint32_t sb = smem_u32(smem);
    const int tid = threadIdx.x, lane = tid & 31, wid = tid >> 5;
    const int warp_m = wid >> 2, warp_n = wid & 3;
    const int rowBase = blockIdx.x << 7;
    const int win0    = blockIdx.x << 5;
    const int h = lane >> 2, i = lane & 3;
    const int dy1 = i >> 1, dx1 = i & 1;

    auto issueW = [&](int c) {
        load_w16(sb + 65536 + (c % 3) * 16384, wph, wpl, 0, (c & 3) * 32, 128);
    };
    issueW(0);

    // ---- attention: each warp handles 4 windows ----------------------------
#pragma unroll
    for (int t = 0; t < 4; t++) {
        const int wl  = wid * 4 + t;
        const int win = win0 + wl;
        const int w   = win & 4095;
        const bool mr = ((w >> 6) == 63);
        const bool mc = ((w & 63) == 63);
        const bf16* base = qkv + (size_t)win * (4 * 384);

        float q[16];
        const bf16* qp = base + i * 384 + h * 16;
#pragma unroll
        for (int d4 = 0; d4 < 4; d4++) {
            float4 v = ld4bf(qp + d4 * 4);
            q[d4 * 4 + 0] = v.x; q[d4 * 4 + 1] = v.y;
            q[d4 * 4 + 2] = v.z; q[d4 * 4 + 3] = v.w;
        }
        float s[4];
#pragma unroll
        for (int j = 0; j < 4; j++) {
            const bf16* kp = base + j * 384 + 128 + h * 16;
            float a = 0.0f;
#pragma unroll
            for (int d4 = 0; d4 < 4; d4++) {
                float4 v = ld4bf(kp + d4 * 4);
                a += q[d4 * 4 + 0] * v.x + q[d4 * 4 + 1] * v.y
                   + q[d4 * 4 + 2] * v.z + q[d4 * 4 + 3] * v.w;
            }
            int dy2 = j >> 1, dx2 = j & 1;
            bool ok = (!mr || dy1 == dy2) && (!mc || dx1 == dx2);
            s[j] = a + __ldg(rpb + ((dy1 - dy2 + 1) * 3 + (dx1 - dx2 + 1)) * 8 + h)
                 + (ok ? 0.0f : -100.0f);
        }
        float mx = fmaxf(fmaxf(s[0], s[1]), fmaxf(s[2], s[3]));
        float p[4], sum = 0.0f;
#pragma unroll
        for (int j = 0; j < 4; j++) { p[j] = expf(s[j] - mx); sum += p[j]; }
        float inv = 1.0f / sum;

        float ov[16];
#pragma unroll
        for (int d = 0; d < 16; d++) ov[d] = 0.0f;
#pragma unroll
        for (int j = 0; j < 4; j++) {
            const bf16* vp = base + j * 384 + 256 + h * 16;
            float pj = p[j] * inv;
#pragma unroll
            for (int d4 = 0; d4 < 4; d4++) {
                float4 v = ld4bf(vp + d4 * 4);
                ov[d4 * 4 + 0] += pj * v.x; ov[d4 * 4 + 1] += pj * v.y;
                ov[d4 * 4 + 2] += pj * v.z; ov[d4 * 4 + 3] += pj * v.w;
            }
        }
        const int row = wl * 4 + i;
#pragma unroll
        for (int d4 = 0; d4 < 4; d4++) {
            const int ch = h * 16 + d4 * 4;
            char* dst = smem + (ch >> 6) * 32768;
            uint32_t o16 = SWZ128((uint32_t)(row * 128 + (ch & 63) * 2));
            float a0 = ov[d4 * 4], a1 = ov[d4 * 4 + 1],
                  a2 = ov[d4 * 4 + 2], a3 = ov[d4 * 4 + 3];
            float h0 = bhi(a0), h1 = bhi(a1), h2v = bhi(a2), h3 = bhi(a3);
            *(uint2*)(dst + o16)         = make_uint2(pk2(h0, h1), pk2(h2v, h3));
            *(uint2*)(dst + 16384 + o16) = make_uint2(pk2(a0 - h0, a1 - h1),
                                                      pk2(a2 - h2v, a3 - h3));
        }
    }
    issueW(1);

    // ---- proj GEMM ----------------------------------------------------------
    float4 acc[4][4];
#pragma unroll
    for (int a = 0; a < 4; a++)
#pragma unroll
        for (int j = 0; j < 4; j++) acc[a][j] = make_float4(0, 0, 0, 0);
#pragma unroll
    for (int c = 0; c < 4; c++) {
        if (c == 3) CP_WAIT0(); else CP_WAIT1();
        __syncthreads();
        mma_half<4, 16384>(acc, sb + (c >> 1) * 32768, c & 1,
                           sb + 65536 + (c % 3) * 16384);
        if (c + 2 <= 3) issueW(c + 2);
    }

    const int r4 = lane >> 2, c2 = (lane & 3) * 2;
#pragma unroll
    for (int mt = 0; mt < 4; mt++)
#pragma unroll
        for (int half = 0; half < 2; half++) {
            const int gr = rowBase + warp_m * 64 + mt * 16 + r4 + half * 8;
            const size_t outRow = (size_t)orig_of(gr);
#pragma unroll
            for (int nt = 0; nt < 4; nt++) {
                const int col = warp_n * 32 + nt * 8 + c2;
                float v0 = half ? acc[mt][nt].z : acc[mt][nt].x;
                float v1 = half ? acc[mt][nt].w : acc[mt][nt].y;
                const float2 sk = *(const float2*)(x + outRow * 128 + col);
                v0 += __ldg(proj_b + col) + sk.x;
                v1 += __ldg(proj_b + col + 1) + sk.y;
                *(float2*)(h2 + outRow * 128 + col) = make_float2(v0, v1);
            }
        }
}

// ---------------------------------------------------------------------------
// Kernel 3: LN2 + MLP1(GELU) + MLP2 + residual, M=64 tiles, interleaved.
// L2A 32KB @0 | M1 32KB @32768 | W 3x16KB @65536 -> 112KB.  16 chunks.
// ---------------------------------------------------------------------------
__global__ __launch_bounds__(256, 2) void mlp_kernel(
    const float* __restrict__ h2, const float* __restrict__ g2,
    const float* __restrict__ b2,
    const bf16* __restrict__ w1h, const bf16* __restrict__ w1l,
    const float* __restrict__ bb1,
    const bf16* __restrict__ w2h, const bf16* __restrict__ w2l,
    const float* __restrict__ bb2, float* __restrict__ out)
{
    extern __shared__ char smem[];
    const uint32_t sb = smem_u32(smem);
    const int tid = threadIdx.x, lane = tid & 31, wid = tid >> 5;
    const int warp_m = wid >> 2, warp_n = wid & 3;
    const int rowBase = blockIdx.x << 6;   // 64 rows per CTA
    const int r4 = lane >> 2, c2 = (lane & 3) * 2;

    auto issueW = [&](int c) {
        const int seg = c >> 2, sub = c & 3;
        const uint32_t dst = sb + 65536 + (c % 3) * 16384;
        if (seg == 0)      load_w16(dst, w1h, w1l, 0,   sub * 32, 128);
        else if (seg == 1) load_w16(dst, w2h, w2l, 0,   sub * 32, 256);
        else if (seg == 2) load_w16(dst, w1h, w1l, 128, sub * 32, 128);
        else               load_w16(dst, w2h, w2l, 0, 128 + sub * 32, 256);
    };

    issueW(0);
    ln_to_smem<false, 64>(h2, g2, b2, smem, rowBase);
    issueW(1);

    float4 acc2[2][4];
#pragma unroll
    for (int a = 0; a < 2; a++)
#pragma unroll
        for (int j = 0; j < 4; j++) acc2[a][j] = make_float4(0, 0, 0, 0);

#pragma unroll
    for (int seg = 0; seg < 4; seg++) {
        const bool isM1 = (seg & 1) == 0;       // mlp1 segments: 0, 2
        float4 acc1[2][4];
        if (isM1) {
#pragma unroll
            for (int a = 0; a < 2; a++)
#pragma unroll
                for (int j = 0; j < 4; j++) acc1[a][j] = make_float4(0, 0, 0, 0);
        }
        const uint32_t aB = isM1 ? sb : sb + 32768;
#pragma unroll
        for (int hh = 0; hh < 4; hh++) {
            const int c = seg * 4 + hh;
            if (c == 15) CP_WAIT0(); else CP_WAIT1();
            __syncthreads();
            mma_half<2, 8192>(isM1 ? acc1 : acc2, aB + (hh >> 1) * 16384,
                              hh & 1, sb + 65536 + (c % 3) * 16384);
            if (c + 2 <= 15) issueW(c + 2);
        }
        if (isM1) {
            const int bOff = (seg == 0) ? 0 : 128;
#pragma unroll
            for (int mt = 0; mt < 2; mt++)
#pragma unroll
                for (int half = 0; half < 2; half++) {
                    const int row = warp_m * 32 + mt * 16 + r4 + half * 8;
#pragma unroll
                    for (int nt = 0; nt < 4; nt++) {
                        const int ch = warp_n * 32 + nt * 8 + c2;
                        float v0 = half ? acc1[mt][nt].z : acc1[mt][nt].x;
                        float v1 = half ? acc1[mt][nt].w : acc1[mt][nt].y;
                        v0 += __ldg(bb1 + bOff + ch);
                        v1 += __ldg(bb1 + bOff + ch + 1);
                        v0 = v0 * normcdff(v0);
                        v1 = v1 * normcdff(v1);
                        float h0 = bhi(v0), h1 = bhi(v1);
                        char* dst = smem + 32768 + (ch >> 6) * 16384;
                        uint32_t o16 = SWZ128((uint32_t)(row * 128 + (ch & 63) * 2));
                        *(uint32_t*)(dst + o16)        = pk2(h0, h1);
                        *(uint32_t*)(dst + 8192 + o16) = pk2(v0 - h0, v1 - h1);
                    }
                }
        }
    }

    // ---- final epilogue: out = acc2 + b2 + h2 -------------------------------
#pragma unroll
    for (int mt = 0; mt < 2; mt++)
#pragma unroll
        for (int half = 0; half < 2; half++) {
            const int gr = rowBase + warp_m * 32 + mt * 16 + r4 + half * 8;
#pragma unroll
            for (int nt = 0; nt < 4; nt++) {
                const int col = warp_n * 32 + nt * 8 + c2;
                float v0 = half ? acc2[mt][nt].z : acc2[mt][nt].x;
                float v1 = half ? acc2[mt][nt].w : acc2[mt][nt].y;
                const float2 sk = *(const float2*)(h2 + (size_t)gr * 128 + col);
                v0 += __ldg(bb2 + col) + sk.x;
                v1 += __ldg(bb2 + col + 1) + sk.y;
                *(float2*)(out + (size_t)gr * 128 + col) = make_float2(v0, v1);
            }
        }
}

// ---------------------------------------------------------------------------
extern "C" void kernel_launch(void* const* d_in, const int* in_sizes, int n_in,
                              void* d_out, int out_size)
{
    const float* x      = (const float*)d_in[0];
    const float* qkv_w  = (const float*)d_in[1];
    const float* qkv_b  = (const float*)d_in[2];
    const float* proj_w = (const float*)d_in[3];
    const float* proj_b = (const float*)d_in[4];
    const float* rpb    = (const float*)d_in[5];
    const float* g1     = (const float*)d_in[6];
    const float* b1     = (const float*)d_in[7];
    const float* g2     = (const float*)d_in[8];
    const float* b2     = (const float*)d_in[9];
    const float* w1     = (const float*)d_in[10];
    const float* bb1    = (const float*)d_in[11];
    const float* w2     = (const float*)d_in[12];
    const float* bb2    = (const float*)d_in[13];
    float* out = (float*)d_out;

    float *h2;
    bf16 *qkv, *wqh, *wql, *wph, *wpl, *w1h, *w1l, *w2h, *w2l;
    cudaGetSymbolAddress((void**)&qkv, g_qkv);
    cudaGetSymbolAddress((void**)&h2,  g_h2);
    cudaGetSymbolAddress((void**)&wqh, g_wqh);
    cudaGetSymbolAddress((void**)&wql, g_wql);
    cudaGetSymbolAddress((void**)&wph, g_wph);
    cudaGetSymbolAddress((void**)&wpl, g_wpl);
    cudaGetSymbolAddress((void**)&w1h, g_w1h);
    cudaGetSymbolAddress((void**)&w1l, g_w1l);
    cudaGetSymbolAddress((void**)&w2h, g_w2h);
    cudaGetSymbolAddress((void**)&w2l, g_w2l);

    cudaFuncSetAttribute(qkv_kernel,      cudaFuncAttributeMaxDynamicSharedMemorySize, 114688);
    cudaFuncSetAttribute(attnproj_kernel, cudaFuncAttributeMaxDynamicSharedMemorySize, 114688);
    cudaFuncSetAttribute(mlp_kernel,      cudaFuncAttributeMaxDynamicSharedMemorySize, 114688);

    wconv_all<<<512, 256>>>(qkv_w, proj_w, w1, w2,
                            wqh, wql, wph, wpl, w1h, w1l, w2h, w2l);

    qkv_kernel<<<TOK / 128, 256, 114688>>>(x, g1, b1, wqh, wql, qkv_b, qkv);
    attnproj_kernel<<<TOK / 128, 256, 114688>>>(qkv, rpb, wph, wpl, proj_b, x, h2);
    mlp_kernel<<<TOK / 64, 256, 114688>>>(h2, g2, b2, w1h, w1l, bb1,
                                          w2h, w2l, bb2, out);
}

// round 9
// speedup vs baseline: 2.3670x; 1.4094x over previous
#include <cuda_runtime.h>
#include <cuda_bf16.h>
#include <math.h>
#include <stdint.h>

// ---------------------------------------------------------------------------
// Swin block: B=32, H=W=128, C=128, WS=2, SS=1, NH=8, HD=16
// 3 fused kernels. GEMMs: mma.sync bf16 2-pass (A rounded to bf16, weights
// kept as hi/lo bf16 pair -> D = Ahi*Bhi + Ahi*Blo). 3-stage weight pipeline.
// ---------------------------------------------------------------------------

#define TOK   524288

typedef __nv_bfloat16 bf16;

__device__ bf16  g_qkv[(size_t)TOK * 384];   // bf16 qkv (q pre-scaled)
__device__ float g_h2 [(size_t)TOK * 128];
__device__ bf16  g_wqh[384 * 128], g_wql[384 * 128];
__device__ bf16  g_wph[128 * 128], g_wpl[128 * 128];
__device__ bf16  g_w1h[256 * 128], g_w1l[256 * 128];
__device__ bf16  g_w2h[128 * 256], g_w2l[128 * 256];

// ---------------------------------------------------------------------------
__device__ __forceinline__ uint32_t smem_u32(const void* p) {
    uint32_t a;
    asm("{ .reg .u64 t; cvta.to.shared.u64 t, %1; cvt.u32.u64 %0, t; }"
        : "=r"(a) : "l"(p));
    return a;
}

#define SWZ128(o) ((o) ^ (((o) >> 3) & 0x70))
#define SWZ64(o)  ((o) ^ (((o) >> 3) & 0x30))

#define CP_ASYNC16(dst, src) \
    asm volatile("cp.async.cg.shared.global [%0], [%1], 16;" \
                 :: "r"(dst), "l"(src) : "memory")
#define CP_COMMIT()  asm volatile("cp.async.commit_group;" ::: "memory")
#define CP_WAIT0()   asm volatile("cp.async.wait_group 0;" ::: "memory")
#define CP_WAIT1()   asm volatile("cp.async.wait_group 1;" ::: "memory")

__device__ __forceinline__ void ldsm4(uint32_t r[4], uint32_t addr) {
    asm volatile("ldmatrix.sync.aligned.m8n8.x4.shared.b16 {%0,%1,%2,%3}, [%4];"
                 : "=r"(r[0]), "=r"(r[1]), "=r"(r[2]), "=r"(r[3]) : "r"(addr));
}

__device__ __forceinline__ void mma_bf16(float4& d, const uint32_t a[4],
                                         const uint32_t b[2]) {
    asm volatile(
        "mma.sync.aligned.m16n8k16.row.col.f32.bf16.bf16.f32 "
        "{%0,%1,%2,%3}, {%4,%5,%6,%7}, {%8,%9}, {%0,%1,%2,%3};"
        : "+f"(d.x), "+f"(d.y), "+f"(d.z), "+f"(d.w)
        : "r"(a[0]), "r"(a[1]), "r"(a[2]), "r"(a[3]), "r"(b[0]), "r"(b[1]));
}

__device__ __forceinline__ int orig_of(int r) {
    int win = r >> 2, s = r & 3;
    int b  = win >> 12;
    int w  = win & 4095;
    int wh = w >> 6, ww = w & 63;
    int ii = ((wh << 1) + (s >> 1) + 1) & 127;
    int jj = ((ww << 1) + (s & 1) + 1) & 127;
    return (b << 14) + (ii << 7) + jj;
}

__device__ __forceinline__ uint32_t pk2(float a, float b) {
    __nv_bfloat162 t = __floats2bfloat162_rn(a, b);
    return *(uint32_t*)&t;
}
__device__ __forceinline__ float bhi(float v) {
    return __bfloat162float(__float2bfloat16(v));
}
__device__ __forceinline__ float4 ld4bf(const bf16* p) {
    uint2 u = __ldg((const uint2*)p);
    float2 fa = __bfloat1622float2(*(__nv_bfloat162*)&u.x);
    float2 fb = __bfloat1622float2(*(__nv_bfloat162*)&u.y);
    return make_float4(fa.x, fa.y, fb.x, fb.y);
}
// gelu via HW tanh (tanh.approx.f32, sm_75+)
__device__ __forceinline__ float gelu_t(float x) {
    float u = 0.7978845608f * x * fmaf(0.044715f, x * x, 1.0f);
    float t;
    asm("tanh.approx.f32 %0, %1;" : "=f"(t) : "f"(u));
    return 0.5f * x * (1.0f + t);
}

// ---------------------------------------------------------------------------
// LN of ROWS rows -> plain bf16 SW128 A region at smem offset 0.
// Layout: 2 k64-chunks of ROWS*128 bytes each.
// ---------------------------------------------------------------------------
template <bool GATHER, int ROWS>
__device__ __forceinline__ void ln_to_smem(
    const float* __restrict__ in, const float* __restrict__ gamma,
    const float* __restrict__ beta, char* smem, int rowBase)
{
    const int tid = threadIdx.x, lane = tid & 31, wid = tid >> 5;
    const float4 g = *(const float4*)(gamma + lane * 4);
    const float4 b = *(const float4*)(beta  + lane * 4);
    const uint32_t colOff = (uint32_t)((lane & 15) * 8);
    char* dhi = smem + (lane >> 4) * (ROWS * 128);
#pragma unroll 4
    for (int r = wid; r < ROWS; r += 8) {
        int src = GATHER ? orig_of(rowBase + r) : (rowBase + r);
        float4 v = __ldg((const float4*)(in + (size_t)src * 128 + lane * 4));
        float s = v.x + v.y + v.z + v.w;
        float q = v.x * v.x + v.y * v.y + v.z * v.z + v.w * v.w;
#pragma unroll
        for (int o = 16; o; o >>= 1) {
            s += __shfl_xor_sync(0xffffffffu, s, o);
            q += __shfl_xor_sync(0xffffffffu, q, o);
        }
        float mean = s * (1.0f / 128.0f);
        float rstd = rsqrtf(q * (1.0f / 128.0f) - mean * mean + 1e-5f);
        float o0 = (v.x - mean) * rstd * g.x + b.x;
        float o1 = (v.y - mean) * rstd * g.y + b.y;
        float o2 = (v.z - mean) * rstd * g.z + b.z;
        float o3 = (v.w - mean) * rstd * g.w + b.w;
        uint32_t o16 = SWZ128((uint32_t)(r * 128) + colOff);
        *(uint2*)(dhi + o16) = make_uint2(pk2(o0, o1), pk2(o2, o3));
    }
}

// ---------------------------------------------------------------------------
// cp.async one 128(N) x 32(k) bf16 hi/lo weight chunk -> 16KB SW64 region.
// ---------------------------------------------------------------------------
__device__ __forceinline__ void load_w16(
    uint32_t dst, const bf16* __restrict__ hi, const bf16* __restrict__ lo,
    int rowOff, int kOff, int kStride)
{
    const int tid = threadIdx.x, c16 = tid & 3;
#pragma unroll
    for (int it = 0; it < 2; it++) {
        int row = (tid >> 2) + it * 64;
        uint32_t d = dst + SWZ64((uint32_t)(row * 64 + c16 * 16));
        const size_t s = (size_t)(rowOff + row) * kStride + kOff + c16 * 8;
        CP_ASYNC16(d, hi + s);
        CP_ASYNC16(d + 8192, lo + s);
    }
    CP_COMMIT();
}

// ---------------------------------------------------------------------------
// k32 half-chunk warp MMA, 2-pass: acc += A*(Bhi + Blo).
// A: plain bf16 SW128 k64-chunk at aBase.  B: 16KB SW64 (hi 8KB | lo 8KB).
// ---------------------------------------------------------------------------
template <int MT>
__device__ __forceinline__ void mma_half(
    float4 (&acc)[MT][4], uint32_t aBase, int khalf, uint32_t bBase)
{
    const int lane = threadIdx.x & 31, wid = threadIdx.x >> 5;
    const int warp_m = wid >> 2, warp_n = wid & 3;
    const int arow = warp_m * (MT * 16) + (lane & 15);
    const int akb  = (lane >> 4) * 8;
    const int brow = warp_n * 32 + ((lane >> 4) & 1) * 8 + (lane & 7);
    const int bkb  = ((lane >> 3) & 1) * 8;
#pragma unroll
    for (int ks = 0; ks < 2; ks++) {
        const int kA = (khalf * 32 + ks * 16 + akb) * 2;
        const int kB = (ks * 16 + bkb) * 2;
        uint32_t bh[2][4], bl[2][4];
#pragma unroll
        for (int i = 0; i < 2; i++) {
            uint32_t boff = SWZ64((uint32_t)((brow + i * 16) * 64 + kB));
            ldsm4(bh[i], bBase + boff);
            ldsm4(bl[i], bBase + 8192 + boff);
        }
#pragma unroll
        for (int mt = 0; mt < MT; mt++) {
            uint32_t aoff = SWZ128((uint32_t)((arow + mt * 16) * 128 + kA));
            uint32_t ah[4];
            ldsm4(ah, aBase + aoff);
#pragma unroll
            for (int nt = 0; nt < 4; nt++) {
                mma_bf16(acc[mt][nt], ah, &bh[nt >> 1][(nt & 1) * 2]);
                mma_bf16(acc[mt][nt], ah, &bl[nt >> 1][(nt & 1) * 2]);
            }
        }
    }
}

// ---------------------------------------------------------------------------
// Weight transpose + split (all 4 weights, one launch)
// ---------------------------------------------------------------------------
__global__ void wconv_all(
    const float* __restrict__ qkv_w, const float* __restrict__ proj_w,
    const float* __restrict__ w1, const float* __restrict__ w2,
    bf16* wqh, bf16* wql, bf16* wph, bf16* wpl,
    bf16* w1h, bf16* w1l, bf16* w2h, bf16* w2l)
{
    int idx = blockIdx.x * 256 + threadIdx.x;   // 131072 total
    const float* w; bf16 *hi, *lo; int K, N;
    if (idx < 49152)       { w = qkv_w;  hi = wqh; lo = wql; K = 128; N = 384; }
    else if (idx < 65536)  { idx -= 49152; w = proj_w; hi = wph; lo = wpl; K = 128; N = 128; }
    else if (idx < 98304)  { idx -= 65536; w = w1; hi = w1h; lo = w1l; K = 128; N = 256; }
    else                   { idx -= 98304; w = w2; hi = w2h; lo = w2l; K = 256; N = 128; }
    int n = idx / K, k = idx - n * K;
    float v = w[(size_t)k * N + n];
    float h = bhi(v);
    hi[idx] = __float2bfloat16(v);
    lo[idx] = __float2bfloat16(v - h);
}

// ---------------------------------------------------------------------------
// Kernel 1: LN1(+gather) + qkv GEMM -> bf16 qkv.
// A 32KB @0 | W 3x16KB @32768 -> 80KB.  12 k32 chunks, 3-stage.
// ---------------------------------------------------------------------------
__global__ __launch_bounds__(256, 2) void qkv_kernel(
    const float* __restrict__ x, const float* __restrict__ g1,
    const float* __restrict__ b1,
    const bf16* __restrict__ wqh, const bf16* __restrict__ wql,
    const float* __restrict__ qkv_b, bf16* __restrict__ qkv)
{
    extern __shared__ char smem[];
    const uint32_t sb = smem_u32(smem);
    const int tid = threadIdx.x, lane = tid & 31, wid = tid >> 5;
    const int warp_m = wid >> 2, warp_n = wid & 3;
    const int rowBase = blockIdx.x << 7;
    const int r4 = lane >> 2, c2 = (lane & 3) * 2;

    auto issueW = [&](int c) {
        load_w16(sb + 32768 + (c % 3) * 16384, wqh, wql,
                 (c >> 2) * 128, (c & 3) * 32, 128);
    };

    issueW(0);
    ln_to_smem<true, 128>(x, g1, b1, smem, rowBase);
    issueW(1);

#pragma unroll
    for (int p = 0; p < 3; p++) {
        float4 acc[4][4];
#pragma unroll
        for (int i = 0; i < 4; i++)
#pragma unroll
            for (int j = 0; j < 4; j++) acc[i][j] = make_float4(0, 0, 0, 0);
#pragma unroll
        for (int h = 0; h < 4; h++) {
            const int c = p * 4 + h;
            if (c == 11) CP_WAIT0(); else CP_WAIT1();
            __syncthreads();
            mma_half<4>(acc, sb + (h >> 1) * 16384, h & 1,
                        sb + 32768 + (c % 3) * 16384);
            if (c + 2 <= 11) issueW(c + 2);
        }
        const float scale = (p == 0) ? 0.25f : 1.0f;
#pragma unroll
        for (int mt = 0; mt < 4; mt++)
#pragma unroll
            for (int half = 0; half < 2; half++) {
                const int gr = rowBase + warp_m * 64 + mt * 16 + r4 + half * 8;
#pragma unroll
                for (int nt = 0; nt < 4; nt++) {
                    const int col = p * 128 + warp_n * 32 + nt * 8 + c2;
                    float v0 = half ? acc[mt][nt].z : acc[mt][nt].x;
                    float v1 = half ? acc[mt][nt].w : acc[mt][nt].y;
                    v0 = (v0 + __ldg(qkv_b + col)) * scale;
                    v1 = (v1 + __ldg(qkv_b + col + 1)) * scale;
                    *(uint32_t*)(qkv + (size_t)gr * 384 + col) = pk2(v0, v1);
                }
            }
    }
}

// ---------------------------------------------------------------------------
// Kernel 2: window attention (bf16 qkv) + proj GEMM + residual scatter.
// O 32KB @0 | W 3x16KB @32768 -> 80KB.  4 k32 chunks, 3-stage.
// ---------------------------------------------------------------------------
__global__ __launch_bounds__(256, 2) void attnproj_kernel(
    const bf16* __restrict__ qkv, const float* __restrict__ rpb,
    const bf16* __restrict__ wph, const bf16* __restrict__ wpl,
    const float* __restrict__ proj_b, const float* __restrict__ x,
    float* __restrict__ h2)
{
    extern __shared__ char smem[];
    const uint32_t sb = smem_u32(smem);
    const int tid = threadIdx.x, lane = tid & 31, wid = tid >> 5;
    const int warp_m = wid >> 2, warp_n = wid & 3;
    const int rowBase = blockIdx.x << 7;
    const int win0    = blockIdx.x << 5;
    const int h = lane >> 2, i = lane & 3;
    const int dy1 = i >> 1, dx1 = i & 1;

    auto issueW = [&](int c) {
        load_w16(sb + 32768 + (c % 3) * 16384, wph, wpl, 0, (c & 3) * 32, 128);
    };
    issueW(0);

    // ---- attention: each warp handles 4 windows ----------------------------
#pragma unroll
    for (int t = 0; t < 4; t++) {
        const int wl  = wid * 4 + t;
        const int win = win0 + wl;
        const int w   = win & 4095;
        const bool mr = ((w >> 6) == 63);
        const bool mc = ((w & 63) == 63);
        const bf16* base = qkv + (size_t)win * (4 * 384);

        float q[16];
        const bf16* qp = base + i * 384 + h * 16;
#pragma unroll
        for (int d4 = 0; d4 < 4; d4++) {
            float4 v = ld4bf(qp + d4 * 4);
            q[d4 * 4 + 0] = v.x; q[d4 * 4 + 1] = v.y;
            q[d4 * 4 + 2] = v.z; q[d4 * 4 + 3] = v.w;
        }
        float s[4];
#pragma unroll
        for (int j = 0; j < 4; j++) {
            const bf16* kp = base + j * 384 + 128 + h * 16;
            float a = 0.0f;
#pragma unroll
            for (int d4 = 0; d4 < 4; d4++) {
                float4 v = ld4bf(kp + d4 * 4);
                a += q[d4 * 4 + 0] * v.x + q[d4 * 4 + 1] * v.y
                   + q[d4 * 4 + 2] * v.z + q[d4 * 4 + 3] * v.w;
            }
            int dy2 = j >> 1, dx2 = j & 1;
            bool ok = (!mr || dy1 == dy2) && (!mc || dx1 == dx2);
            s[j] = a + __ldg(rpb + ((dy1 - dy2 + 1) * 3 + (dx1 - dx2 + 1)) * 8 + h)
                 + (ok ? 0.0f : -100.0f);
        }
        float mx = fmaxf(fmaxf(s[0], s[1]), fmaxf(s[2], s[3]));
        float p[4], sum = 0.0f;
#pragma unroll
        for (int j = 0; j < 4; j++) { p[j] = expf(s[j] - mx); sum += p[j]; }
        float inv = 1.0f / sum;

        float ov[16];
#pragma unroll
        for (int d = 0; d < 16; d++) ov[d] = 0.0f;
#pragma unroll
        for (int j = 0; j < 4; j++) {
            const bf16* vp = base + j * 384 + 256 + h * 16;
            float pj = p[j] * inv;
#pragma unroll
            for (int d4 = 0; d4 < 4; d4++) {
                float4 v = ld4bf(vp + d4 * 4);
                ov[d4 * 4 + 0] += pj * v.x; ov[d4 * 4 + 1] += pj * v.y;
                ov[d4 * 4 + 2] += pj * v.z; ov[d4 * 4 + 3] += pj * v.w;
            }
        }
        const int row = wl * 4 + i;
#pragma unroll
        for (int d4 = 0; d4 < 4; d4++) {
            const int ch = h * 16 + d4 * 4;
            char* dst = smem + (ch >> 6) * 16384;
            uint32_t o16 = SWZ128((uint32_t)(row * 128 + (ch & 63) * 2));
            *(uint2*)(dst + o16) = make_uint2(pk2(ov[d4 * 4], ov[d4 * 4 + 1]),
                                              pk2(ov[d4 * 4 + 2], ov[d4 * 4 + 3]));
        }
    }
    issueW(1);

    // ---- proj GEMM ----------------------------------------------------------
    float4 acc[4][4];
#pragma unroll
    for (int a = 0; a < 4; a++)
#pragma unroll
        for (int j = 0; j < 4; j++) acc[a][j] = make_float4(0, 0, 0, 0);
#pragma unroll
    for (int c = 0; c < 4; c++) {
        if (c == 3) CP_WAIT0(); else CP_WAIT1();
        __syncthreads();
        mma_half<4>(acc, sb + (c >> 1) * 16384, c & 1,
                    sb + 32768 + (c % 3) * 16384);
        if (c + 2 <= 3) issueW(c + 2);
    }

    const int r4 = lane >> 2, c2 = (lane & 3) * 2;
#pragma unroll
    for (int mt = 0; mt < 4; mt++)
#pragma unroll
        for (int half = 0; half < 2; half++) {
            const int gr = rowBase + warp_m * 64 + mt * 16 + r4 + half * 8;
            const size_t outRow = (size_t)orig_of(gr);
#pragma unroll
            for (int nt = 0; nt < 4; nt++) {
                const int col = warp_n * 32 + nt * 8 + c2;
                float v0 = half ? acc[mt][nt].z : acc[mt][nt].x;
                float v1 = half ? acc[mt][nt].w : acc[mt][nt].y;
                const float2 sk = *(const float2*)(x + outRow * 128 + col);
                v0 += __ldg(proj_b + col) + sk.x;
                v1 += __ldg(proj_b + col + 1) + sk.y;
                *(float2*)(h2 + outRow * 128 + col) = make_float2(v0, v1);
            }
        }
}

// ---------------------------------------------------------------------------
// Kernel 3: LN2 + MLP1(GELU) + MLP2 + residual, M=64 tiles, interleaved.
// L2A 16KB @0 | M1 32KB @16384 | W 3x16KB @49152 -> 96KB.  16 chunks.
// ---------------------------------------------------------------------------
__global__ __launch_bounds__(256, 2) void mlp_kernel(
    const float* __restrict__ h2, const float* __restrict__ g2,
    const float* __restrict__ b2,
    const bf16* __restrict__ w1h, const bf16* __restrict__ w1l,
    const float* __restrict__ bb1,
    const bf16* __restrict__ w2h, const bf16* __restrict__ w2l,
    const float* __restrict__ bb2, float* __restrict__ out)
{
    extern __shared__ char smem[];
    const uint32_t sb = smem_u32(smem);
    const int tid = threadIdx.x, lane = tid & 31, wid = tid >> 5;
    const int warp_m = wid >> 2, warp_n = wid & 3;
    const int rowBase = blockIdx.x << 6;   // 64 rows per CTA
    const int r4 = lane >> 2, c2 = (lane & 3) * 2;

    auto issueW = [&](int c) {
        const int seg = c >> 2, sub = c & 3;
        const uint32_t dst = sb + 49152 + (c % 3) * 16384;
        if (seg == 0)      load_w16(dst, w1h, w1l, 0,   sub * 32, 128);
        else if (seg == 1) load_w16(dst, w2h, w2l, 0,   sub * 32, 256);
        else if (seg == 2) load_w16(dst, w1h, w1l, 128, sub * 32, 128);
        else               load_w16(dst, w2h, w2l, 0, 128 + sub * 32, 256);
    };

    issueW(0);
    ln_to_smem<false, 64>(h2, g2, b2, smem, rowBase);
    issueW(1);

    float4 acc2[2][4];
#pragma unroll
    for (int a = 0; a < 2; a++)
#pragma unroll
        for (int j = 0; j < 4; j++) acc2[a][j] = make_float4(0, 0, 0, 0);

#pragma unroll
    for (int seg = 0; seg < 4; seg++) {
        const bool isM1 = (seg & 1) == 0;       // mlp1 segments: 0, 2
        float4 acc1[2][4];
        if (isM1) {
#pragma unroll
            for (int a = 0; a < 2; a++)
#pragma unroll
                for (int j = 0; j < 4; j++) acc1[a][j] = make_float4(0, 0, 0, 0);
        }
        // A base: L2A for mlp1; M1 chunks 0-1 (seg1) or 2-3 (seg3) for mlp2
        const uint32_t aB = isM1 ? sb : (sb + 16384 + (seg == 3 ? 16384 : 0));
#pragma unroll
        for (int hh = 0; hh < 4; hh++) {
            const int c = seg * 4 + hh;
            if (c == 15) CP_WAIT0(); else CP_WAIT1();
            __syncthreads();
            mma_half<2>(isM1 ? acc1 : acc2, aB + (hh >> 1) * 8192,
                        hh & 1, sb + 49152 + (c % 3) * 16384);
            if (c + 2 <= 15) issueW(c + 2);
        }
        if (isM1) {
            const int bOff = (seg == 0) ? 0 : 128;
#pragma unroll
            for (int mt = 0; mt < 2; mt++)
#pragma unroll
                for (int half = 0; half < 2; half++) {
                    const int row = warp_m * 32 + mt * 16 + r4 + half * 8;
#pragma unroll
                    for (int nt = 0; nt < 4; nt++) {
                        const int ch = bOff + warp_n * 32 + nt * 8 + c2;
                        float v0 = half ? acc1[mt][nt].z : acc1[mt][nt].x;
                        float v1 = half ? acc1[mt][nt].w : acc1[mt][nt].y;
                        v0 = gelu_t(v0 + __ldg(bb1 + ch));
                        v1 = gelu_t(v1 + __ldg(bb1 + ch + 1));
                        char* dst = smem + 16384 + (ch >> 6) * 8192;
                        uint32_t o16 = SWZ128((uint32_t)(row * 128 + (ch & 63) * 2));
                        *(uint32_t*)(dst + o16) = pk2(v0, v1);
                    }
                }
        }
    }

    // ---- final epilogue: out = acc2 + b2 + h2 -------------------------------
#pragma unroll
    for (int mt = 0; mt < 2; mt++)
#pragma unroll
        for (int half = 0; half < 2; half++) {
            const int gr = rowBase + warp_m * 32 + mt * 16 + r4 + half * 8;
#pragma unroll
            for (int nt = 0; nt < 4; nt++) {
                const int col = warp_n * 32 + nt * 8 + c2;
                float v0 = half ? acc2[mt][nt].z : acc2[mt][nt].x;
                float v1 = half ? acc2[mt][nt].w : acc2[mt][nt].y;
                const float2 sk = *(const float2*)(h2 + (size_t)gr * 128 + col);
                v0 += __ldg(bb2 + col) + sk.x;
                v1 += __ldg(bb2 + col + 1) + sk.y;
                *(float2*)(out + (size_t)gr * 128 + col) = make_float2(v0, v1);
            }
        }
}

// ---------------------------------------------------------------------------
extern "C" void kernel_launch(void* const* d_in, const int* in_sizes, int n_in,
                              void* d_out, int out_size)
{
    const float* x      = (const float*)d_in[0];
    const float* qkv_w  = (const float*)d_in[1];
    const float* qkv_b  = (const float*)d_in[2];
    const float* proj_w = (const float*)d_in[3];
    const float* proj_b = (const float*)d_in[4];
    const float* rpb    = (const float*)d_in[5];
    const float* g1     = (const float*)d_in[6];
    const float* b1     = (const float*)d_in[7];
    const float* g2     = (const float*)d_in[8];
    const float* b2     = (const float*)d_in[9];
    const float* w1     = (const float*)d_in[10];
    const float* bb1    = (const float*)d_in[11];
    const float* w2     = (const float*)d_in[12];
    const float* bb2    = (const float*)d_in[13];
    float* out = (float*)d_out;

    float *h2;
    bf16 *qkv, *wqh, *wql, *wph, *wpl, *w1h, *w1l, *w2h, *w2l;
    cudaGetSymbolAddress((void**)&qkv, g_qkv);
    cudaGetSymbolAddress((void**)&h2,  g_h2);
    cudaGetSymbolAddress((void**)&wqh, g_wqh);
    cudaGetSymbolAddress((void**)&wql, g_wql);
    cudaGetSymbolAddress((void**)&wph, g_wph);
    cudaGetSymbolAddress((void**)&wpl, g_wpl);
    cudaGetSymbolAddress((void**)&w1h, g_w1h);
    cudaGetSymbolAddress((void**)&w1l, g_w1l);
    cudaGetSymbolAddress((void**)&w2h, g_w2h);
    cudaGetSymbolAddress((void**)&w2l, g_w2l);

    cudaFuncSetAttribute(qkv_kernel,      cudaFuncAttributeMaxDynamicSharedMemorySize, 81920);
    cudaFuncSetAttribute(attnproj_kernel, cudaFuncAttributeMaxDynamicSharedMemorySize, 81920);
    cudaFuncSetAttribute(mlp_kernel,      cudaFuncAttributeMaxDynamicSharedMemorySize, 98304);

    wconv_all<<<512, 256>>>(qkv_w, proj_w, w1, w2,
                            wqh, wql, wph, wpl, w1h, w1l, w2h, w2l);

    qkv_kernel<<<TOK / 128, 256, 81920>>>(x, g1, b1, wqh, wql, qkv_b, qkv);
    attnproj_kernel<<<TOK / 128, 256, 81920>>>(qkv, rpb, wph, wpl, proj_b, x, h2);
    mlp_kernel<<<TOK / 64, 256, 98304>>>(h2, g2, b2, w1h, w1l, bb1,
                                         w2h, w2l, bb2, out);
}

// round 10
// speedup vs baseline: 2.9334x; 1.2393x over previous
#include <cuda_runtime.h>
#include <cuda_bf16.h>
#include <math.h>
#include <stdint.h>

// ---------------------------------------------------------------------------
// Swin block: B=32, H=W=128, C=128, WS=2, SS=1, NH=8, HD=16
// 3 fused kernels. GEMMs: mma.sync plain bf16 1-pass (error budget calibrated
// across R8-R9: each ~2e-3 branch perturbation -> +3-5e-5 final).
// k64 single-plane weight chunks, 3-stage or static buffers.
// ---------------------------------------------------------------------------

#define TOK   524288

typedef __nv_bfloat16 bf16;

__device__ bf16  g_qkv[(size_t)TOK * 384];   // bf16 qkv (q pre-scaled)
__device__ float g_h2 [(size_t)TOK * 128];
// weights transposed to [N,K] bf16
__device__ bf16  g_wq[384 * 128];
__device__ bf16  g_wp[128 * 128];
__device__ bf16  g_w1[256 * 128];
__device__ bf16  g_w2[128 * 256];

// ---------------------------------------------------------------------------
__device__ __forceinline__ uint32_t smem_u32(const void* p) {
    uint32_t a;
    asm("{ .reg .u64 t; cvta.to.shared.u64 t, %1; cvt.u32.u64 %0, t; }"
        : "=r"(a) : "l"(p));
    return a;
}

#define SWZ128(o) ((o) ^ (((o) >> 3) & 0x70))

#define CP_ASYNC16(dst, src) \
    asm volatile("cp.async.cg.shared.global [%0], [%1], 16;" \
                 :: "r"(dst), "l"(src) : "memory")
#define CP_COMMIT()  asm volatile("cp.async.commit_group;" ::: "memory")
#define CP_WAIT0()   asm volatile("cp.async.wait_group 0;" ::: "memory")
#define CP_WAIT1()   asm volatile("cp.async.wait_group 1;" ::: "memory")

__device__ __forceinline__ void ldsm4(uint32_t r[4], uint32_t addr) {
    asm volatile("ldmatrix.sync.aligned.m8n8.x4.shared.b16 {%0,%1,%2,%3}, [%4];"
                 : "=r"(r[0]), "=r"(r[1]), "=r"(r[2]), "=r"(r[3]) : "r"(addr));
}

__device__ __forceinline__ void mma_bf16(float4& d, const uint32_t a[4],
                                         const uint32_t b[2]) {
    asm volatile(
        "mma.sync.aligned.m16n8k16.row.col.f32.bf16.bf16.f32 "
        "{%0,%1,%2,%3}, {%4,%5,%6,%7}, {%8,%9}, {%0,%1,%2,%3};"
        : "+f"(d.x), "+f"(d.y), "+f"(d.z), "+f"(d.w)
        : "r"(a[0]), "r"(a[1]), "r"(a[2]), "r"(a[3]), "r"(b[0]), "r"(b[1]));
}

__device__ __forceinline__ int orig_of(int r) {
    int win = r >> 2, s = r & 3;
    int b  = win >> 12;
    int w  = win & 4095;
    int wh = w >> 6, ww = w & 63;
    int ii = ((wh << 1) + (s >> 1) + 1) & 127;
    int jj = ((ww << 1) + (s & 1) + 1) & 127;
    return (b << 14) + (ii << 7) + jj;
}

__device__ __forceinline__ uint32_t pk2(float a, float b) {
    __nv_bfloat162 t = __floats2bfloat162_rn(a, b);
    return *(uint32_t*)&t;
}
__device__ __forceinline__ float4 ld4bf(const bf16* p) {
    uint2 u = __ldg((const uint2*)p);
    float2 fa = __bfloat1622float2(*(__nv_bfloat162*)&u.x);
    float2 fb = __bfloat1622float2(*(__nv_bfloat162*)&u.y);
    return make_float4(fa.x, fa.y, fb.x, fb.y);
}
// gelu via HW tanh
__device__ __forceinline__ float gelu_t(float x) {
    float u = 0.7978845608f * x * fmaf(0.044715f, x * x, 1.0f);
    float t;
    asm("tanh.approx.f32 %0, %1;" : "=f"(t) : "f"(u));
    return 0.5f * x * (1.0f + t);
}

// ---------------------------------------------------------------------------
// LN of ROWS rows -> plain bf16 SW128 A region at smem offset 0.
// Layout: 2 k64-chunks of ROWS*128 bytes each.
// ---------------------------------------------------------------------------
template <bool GATHER, int ROWS>
__device__ __forceinline__ void ln_to_smem(
    const float* __restrict__ in, const float* __restrict__ gamma,
    const float* __restrict__ beta, char* smem, int rowBase)
{
    const int tid = threadIdx.x, lane = tid & 31, wid = tid >> 5;
    const float4 g = *(const float4*)(gamma + lane * 4);
    const float4 b = *(const float4*)(beta  + lane * 4);
    const uint32_t colOff = (uint32_t)((lane & 15) * 8);
    char* dhi = smem + (lane >> 4) * (ROWS * 128);
#pragma unroll 4
    for (int r = wid; r < ROWS; r += 8) {
        int src = GATHER ? orig_of(rowBase + r) : (rowBase + r);
        float4 v = __ldg((const float4*)(in + (size_t)src * 128 + lane * 4));
        float s = v.x + v.y + v.z + v.w;
        float q = v.x * v.x + v.y * v.y + v.z * v.z + v.w * v.w;
#pragma unroll
        for (int o = 16; o; o >>= 1) {
            s += __shfl_xor_sync(0xffffffffu, s, o);
            q += __shfl_xor_sync(0xffffffffu, q, o);
        }
        float mean = s * (1.0f / 128.0f);
        float rstd = rsqrtf(q * (1.0f / 128.0f) - mean * mean + 1e-5f);
        float o0 = (v.x - mean) * rstd * g.x + b.x;
        float o1 = (v.y - mean) * rstd * g.y + b.y;
        float o2 = (v.z - mean) * rstd * g.z + b.z;
        float o3 = (v.w - mean) * rstd * g.w + b.w;
        uint32_t o16 = SWZ128((uint32_t)(r * 128) + colOff);
        *(uint2*)(dhi + o16) = make_uint2(pk2(o0, o1), pk2(o2, o3));
    }
}

// ---------------------------------------------------------------------------
// cp.async one 128(N) x 64(k) bf16 weight chunk -> 16KB SW128 region.
// ---------------------------------------------------------------------------
__device__ __forceinline__ void load_wk64(
    uint32_t dst, const bf16* __restrict__ w,
    int rowOff, int kOff, int kStride)
{
    const int tid = threadIdx.x, c16 = tid & 7;
#pragma unroll
    for (int it = 0; it < 4; it++) {
        int row = (tid >> 3) + it * 32;
        uint32_t d = dst + SWZ128((uint32_t)(row * 128 + c16 * 16));
        CP_ASYNC16(d, w + (size_t)(rowOff + row) * kStride + kOff + c16 * 8);
    }
    CP_COMMIT();
}

// ---------------------------------------------------------------------------
// k64 chunk warp MMA, 1-pass.  A: bf16 SW128 k64 region (ROWS rows x 128B).
// B: 16KB SW128 k64 weight chunk (128 N-rows x 128B).
// ---------------------------------------------------------------------------
template <int MT>
__device__ __forceinline__ void mma_k64(
    float4 (&acc)[MT][4], uint32_t aBase, uint32_t bBase)
{
    const int lane = threadIdx.x & 31, wid = threadIdx.x >> 5;
    const int warp_m = wid >> 2, warp_n = wid & 3;
    const int arow = warp_m * (MT * 16) + (lane & 15);
    const int akb  = (lane >> 4) * 8;
    const int brow = warp_n * 32 + ((lane >> 4) & 1) * 8 + (lane & 7);
    const int bkb  = ((lane >> 3) & 1) * 8;
#pragma unroll
    for (int ks = 0; ks < 4; ks++) {
        const int kA = (ks * 16 + akb) * 2;
        const int kB = (ks * 16 + bkb) * 2;
        uint32_t bh[2][4];
#pragma unroll
        for (int i = 0; i < 2; i++) {
            uint32_t boff = SWZ128((uint32_t)((brow + i * 16) * 128 + kB));
            ldsm4(bh[i], bBase + boff);
        }
#pragma unroll
        for (int mt = 0; mt < MT; mt++) {
            uint32_t aoff = SWZ128((uint32_t)((arow + mt * 16) * 128 + kA));
            uint32_t ah[4];
            ldsm4(ah, aBase + aoff);
#pragma unroll
            for (int nt = 0; nt < 4; nt++)
                mma_bf16(acc[mt][nt], ah, &bh[nt >> 1][(nt & 1) * 2]);
        }
    }
}

// ---------------------------------------------------------------------------
// Weight transpose: w[K,N] fp32 -> [N,K] bf16 (all 4 weights, one launch)
// ---------------------------------------------------------------------------
__global__ void wconv_all(
    const float* __restrict__ qkv_w, const float* __restrict__ proj_w,
    const float* __restrict__ w1, const float* __restrict__ w2,
    bf16* wq, bf16* wp, bf16* w1b, bf16* w2b)
{
    int idx = blockIdx.x * 256 + threadIdx.x;   // 131072 total
    const float* w; bf16* o; int K, N;
    if (idx < 49152)       { w = qkv_w;  o = wq;  K = 128; N = 384; }
    else if (idx < 65536)  { idx -= 49152; w = proj_w; o = wp;  K = 128; N = 128; }
    else if (idx < 98304)  { idx -= 65536; w = w1; o = w1b; K = 128; N = 256; }
    else                   { idx -= 98304; w = w2; o = w2b; K = 256; N = 128; }
    int n = idx / K, k = idx - n * K;
    o[idx] = __float2bfloat16(w[(size_t)k * N + n]);
}

// ---------------------------------------------------------------------------
// Kernel 1: LN1(+gather) + qkv GEMM -> bf16 qkv.
// A 32KB @0 | W 3x16KB @32768 -> 80KB.  6 k64 chunks, 3-stage.
// ---------------------------------------------------------------------------
__global__ __launch_bounds__(256, 2) void qkv_kernel(
    const float* __restrict__ x, const float* __restrict__ g1,
    const float* __restrict__ b1, const bf16* __restrict__ wq,
    const float* __restrict__ qkv_b, bf16* __restrict__ qkv)
{
    extern __shared__ char smem[];
    const uint32_t sb = smem_u32(smem);
    const int tid = threadIdx.x, lane = tid & 31, wid = tid >> 5;
    const int warp_m = wid >> 2, warp_n = wid & 3;
    const int rowBase = blockIdx.x << 7;
    const int r4 = lane >> 2, c2 = (lane & 3) * 2;

    auto issueW = [&](int c) {
        load_wk64(sb + 32768 + (c % 3) * 16384, wq,
                  (c >> 1) * 128, (c & 1) * 64, 128);
    };

    issueW(0);
    ln_to_smem<true, 128>(x, g1, b1, smem, rowBase);
    issueW(1);

#pragma unroll
    for (int p = 0; p < 3; p++) {
        float4 acc[4][4];
#pragma unroll
        for (int i = 0; i < 4; i++)
#pragma unroll
            for (int j = 0; j < 4; j++) acc[i][j] = make_float4(0, 0, 0, 0);
#pragma unroll
        for (int h = 0; h < 2; h++) {
            const int c = p * 2 + h;
            if (c == 5) CP_WAIT0(); else CP_WAIT1();
            __syncthreads();
            mma_k64<4>(acc, sb + h * 16384, sb + 32768 + (c % 3) * 16384);
            if (c + 2 <= 5) issueW(c + 2);
        }
        const float scale = (p == 0) ? 0.25f : 1.0f;
#pragma unroll
        for (int mt = 0; mt < 4; mt++)
#pragma unroll
            for (int half = 0; half < 2; half++) {
                const int gr = rowBase + warp_m * 64 + mt * 16 + r4 + half * 8;
#pragma unroll
                for (int nt = 0; nt < 4; nt++) {
                    const int col = p * 128 + warp_n * 32 + nt * 8 + c2;
                    float v0 = half ? acc[mt][nt].z : acc[mt][nt].x;
                    float v1 = half ? acc[mt][nt].w : acc[mt][nt].y;
                    v0 = (v0 + __ldg(qkv_b + col)) * scale;
                    v1 = (v1 + __ldg(qkv_b + col + 1)) * scale;
                    *(uint32_t*)(qkv + (size_t)gr * 384 + col) = pk2(v0, v1);
                }
            }
    }
}

// ---------------------------------------------------------------------------
// Kernel 2: window attention (bf16 qkv) + proj GEMM + residual scatter.
// O 32KB @0 | W 2x16KB static @32768 -> 64KB.  2 k64 chunks.
// ---------------------------------------------------------------------------
__global__ __launch_bounds__(256, 2) void attnproj_kernel(
    const bf16* __restrict__ qkv, const float* __restrict__ rpb,
    const bf16* __restrict__ wp, const float* __restrict__ proj_b,
    const float* __restrict__ x, float* __restrict__ h2)
{
    extern __shared__ char smem[];
    const uint32_t sb = smem_u32(smem);
    const int tid = threadIdx.x, lane = tid & 31, wid = tid >> 5;
    const int warp_m = wid >> 2, warp_n = wid & 3;
    const int rowBase = blockIdx.x << 7;
    const int win0    = blockIdx.x << 5;
    const int h = lane >> 2, i = lane & 3;
    const int dy1 = i >> 1, dx1 = i & 1;

    load_wk64(sb + 32768, wp, 0, 0, 128);    // W chunk 0 (k 0-63)

    // ---- attention: each warp handles 4 windows ----------------------------
#pragma unroll
    for (int t = 0; t < 4; t++) {
        const int wl  = wid * 4 + t;
        const int win = win0 + wl;
        const int w   = win & 4095;
        const bool mr = ((w >> 6) == 63);
        const bool mc = ((w & 63) == 63);
        const bf16* base = qkv + (size_t)win * (4 * 384);

        float q[16];
        const bf16* qp = base + i * 384 + h * 16;
#pragma unroll
        for (int d4 = 0; d4 < 4; d4++) {
            float4 v = ld4bf(qp + d4 * 4);
            q[d4 * 4 + 0] = v.x; q[d4 * 4 + 1] = v.y;
            q[d4 * 4 + 2] = v.z; q[d4 * 4 + 3] = v.w;
        }
        float s[4];
#pragma unroll
        for (int j = 0; j < 4; j++) {
            const bf16* kp = base + j * 384 + 128 + h * 16;
            float a = 0.0f;
#pragma unroll
            for (int d4 = 0; d4 < 4; d4++) {
                float4 v = ld4bf(kp + d4 * 4);
                a += q[d4 * 4 + 0] * v.x + q[d4 * 4 + 1] * v.y
                   + q[d4 * 4 + 2] * v.z + q[d4 * 4 + 3] * v.w;
            }
            int dy2 = j >> 1, dx2 = j & 1;
            bool ok = (!mr || dy1 == dy2) && (!mc || dx1 == dx2);
            s[j] = a + __ldg(rpb + ((dy1 - dy2 + 1) * 3 + (dx1 - dx2 + 1)) * 8 + h)
                 + (ok ? 0.0f : -100.0f);
        }
        float mx = fmaxf(fmaxf(s[0], s[1]), fmaxf(s[2], s[3]));
        float p[4], sum = 0.0f;
#pragma unroll
        for (int j = 0; j < 4; j++) { p[j] = expf(s[j] - mx); sum += p[j]; }
        float inv = 1.0f / sum;

        float ov[16];
#pragma unroll
        for (int d = 0; d < 16; d++) ov[d] = 0.0f;
#pragma unroll
        for (int j = 0; j < 4; j++) {
            const bf16* vp = base + j * 384 + 256 + h * 16;
            float pj = p[j] * inv;
#pragma unroll
            for (int d4 = 0; d4 < 4; d4++) {
                float4 v = ld4bf(vp + d4 * 4);
                ov[d4 * 4 + 0] += pj * v.x; ov[d4 * 4 + 1] += pj * v.y;
                ov[d4 * 4 + 2] += pj * v.z; ov[d4 * 4 + 3] += pj * v.w;
            }
        }
        const int row = wl * 4 + i;
#pragma unroll
        for (int d4 = 0; d4 < 4; d4++) {
            const int ch = h * 16 + d4 * 4;
            char* dst = smem + (ch >> 6) * 16384;
            uint32_t o16 = SWZ128((uint32_t)(row * 128 + (ch & 63) * 2));
            *(uint2*)(dst + o16) = make_uint2(pk2(ov[d4 * 4], ov[d4 * 4 + 1]),
                                              pk2(ov[d4 * 4 + 2], ov[d4 * 4 + 3]));
        }
    }
    load_wk64(sb + 49152, wp, 0, 64, 128);   // W chunk 1 (k 64-127)

    // ---- proj GEMM (2 static chunks, no buffer reuse) -----------------------
    float4 acc[4][4];
#pragma unroll
    for (int a = 0; a < 4; a++)
#pragma unroll
        for (int j = 0; j < 4; j++) acc[a][j] = make_float4(0, 0, 0, 0);

    CP_WAIT1();
    __syncthreads();
    mma_k64<4>(acc, sb, sb + 32768);
    CP_WAIT0();
    __syncthreads();
    mma_k64<4>(acc, sb + 16384, sb + 49152);

    const int r4 = lane >> 2, c2 = (lane & 3) * 2;
#pragma unroll
    for (int mt = 0; mt < 4; mt++)
#pragma unroll
        for (int half = 0; half < 2; half++) {
            const int gr = rowBase + warp_m * 64 + mt * 16 + r4 + half * 8;
            const size_t outRow = (size_t)orig_of(gr);
#pragma unroll
            for (int nt = 0; nt < 4; nt++) {
                const int col = warp_n * 32 + nt * 8 + c2;
                float v0 = half ? acc[mt][nt].z : acc[mt][nt].x;
                float v1 = half ? acc[mt][nt].w : acc[mt][nt].y;
                const float2 sk = *(const float2*)(x + outRow * 128 + col);
                v0 += __ldg(proj_b + col) + sk.x;
                v1 += __ldg(proj_b + col + 1) + sk.y;
                *(float2*)(h2 + outRow * 128 + col) = make_float2(v0, v1);
            }
        }
}

// ---------------------------------------------------------------------------
// Kernel 3: LN2 + MLP1(GELU) + MLP2 + residual, M=64 tiles, interleaved.
// L2A 16KB @0 | M1 32KB @16384 | W 3x16KB @49152 -> 96KB.  8 k64 chunks.
// seg0: W1 rows0-127 -> gelu -> M1[0:2];  seg1: W2 k0-127 (acc2);
// seg2: W1 rows128-255 -> gelu -> M1[2:4]; seg3: W2 k128-255 (acc2).
// ---------------------------------------------------------------------------
__global__ __launch_bounds__(256, 2) void mlp_kernel(
    const float* __restrict__ h2, const float* __restrict__ g2,
    const float* __restrict__ b2,
    const bf16* __restrict__ w1, const float* __restrict__ bb1,
    const bf16* __restrict__ w2, const float* __restrict__ bb2,
    float* __restrict__ out)
{
    extern __shared__ char smem[];
    const uint32_t sb = smem_u32(smem);
    const int tid = threadIdx.x, lane = tid & 31, wid = tid >> 5;
    const int warp_m = wid >> 2, warp_n = wid & 3;
    const int rowBase = blockIdx.x << 6;   // 64 rows per CTA
    const int r4 = lane >> 2, c2 = (lane & 3) * 2;

    auto issueW = [&](int c) {
        const int seg = c >> 1, sub = c & 1;
        const uint32_t dst = sb + 49152 + (c % 3) * 16384;
        if (seg == 0)      load_wk64(dst, w1, 0,   sub * 64, 128);
        else if (seg == 1) load_wk64(dst, w2, 0,   sub * 64, 256);
        else if (seg == 2) load_wk64(dst, w1, 128, sub * 64, 128);
        else               load_wk64(dst, w2, 0, 128 + sub * 64, 256);
    };

    issueW(0);
    ln_to_smem<false, 64>(h2, g2, b2, smem, rowBase);
    issueW(1);

    float4 acc2[2][4];
#pragma unroll
    for (int a = 0; a < 2; a++)
#pragma unroll
        for (int j = 0; j < 4; j++) acc2[a][j] = make_float4(0, 0, 0, 0);

#pragma unroll
    for (int seg = 0; seg < 4; seg++) {
        const bool isM1 = (seg & 1) == 0;
        float4 acc1[2][4];
        if (isM1) {
#pragma unroll
            for (int a = 0; a < 2; a++)
#pragma unroll
                for (int j = 0; j < 4; j++) acc1[a][j] = make_float4(0, 0, 0, 0);
        }
        // A base: L2A for mlp1; M1 k-chunks (0,1) for seg1, (2,3) for seg3
        const uint32_t aB = isM1 ? sb : (sb + 16384 + (seg == 3 ? 16384 : 0));
#pragma unroll
        for (int hh = 0; hh < 2; hh++) {
            const int c = seg * 2 + hh;
            if (c == 7) CP_WAIT0(); else CP_WAIT1();
            __syncthreads();
            if (isM1)
                mma_k64<2>(acc1, aB + hh * 8192, sb + 49152 + (c % 3) * 16384);
            else
                mma_k64<2>(acc2, aB + hh * 8192, sb + 49152 + (c % 3) * 16384);
            if (c + 2 <= 7) issueW(c + 2);
        }
        if (isM1) {
            const int bOff = (seg == 0) ? 0 : 128;
#pragma unroll
            for (int mt = 0; mt < 2; mt++)
#pragma unroll
                for (int half = 0; half < 2; half++) {
                    const int row = warp_m * 32 + mt * 16 + r4 + half * 8;
#pragma unroll
                    for (int nt = 0; nt < 4; nt++) {
                        const int ch = bOff + warp_n * 32 + nt * 8 + c2;
                        float v0 = half ? acc1[mt][nt].z : acc1[mt][nt].x;
                        float v1 = half ? acc1[mt][nt].w : acc1[mt][nt].y;
                        v0 = gelu_t(v0 + __ldg(bb1 + ch));
                        v1 = gelu_t(v1 + __ldg(bb1 + ch + 1));
                        char* dst = smem + 16384 + (ch >> 6) * 8192;
                        uint32_t o16 = SWZ128((uint32_t)(row * 128 + (ch & 63) * 2));
                        *(uint32_t*)(dst + o16) = pk2(v0, v1);
                    }
                }
        }
    }

    // ---- final epilogue: out = acc2 + b2 + h2 -------------------------------
#pragma unroll
    for (int mt = 0; mt < 2; mt++)
#pragma unroll
        for (int half = 0; half < 2; half++) {
            const int gr = rowBase + warp_m * 32 + mt * 16 + r4 + half * 8;
#pragma unroll
            for (int nt = 0; nt < 4; nt++) {
                const int col = warp_n * 32 + nt * 8 + c2;
                float v0 = half ? acc2[mt][nt].z : acc2[mt][nt].x;
                float v1 = half ? acc2[mt][nt].w : acc2[mt][nt].y;
                const float2 sk = *(const float2*)(h2 + (size_t)gr * 128 + col);
                v0 += __ldg(bb2 + col) + sk.x;
                v1 += __ldg(bb2 + col + 1) + sk.y;
                *(float2*)(out + (size_t)gr * 128 + col) = make_float2(v0, v1);
            }
        }
}

// ---------------------------------------------------------------------------
extern "C" void kernel_launch(void* const* d_in, const int* in_sizes, int n_in,
                              void* d_out, int out_size)
{
    const float* x      = (const float*)d_in[0];
    const float* qkv_w  = (const float*)d_in[1];
    const float* qkv_b  = (const float*)d_in[2];
    const float* proj_w = (const float*)d_in[3];
    const float* proj_b = (const float*)d_in[4];
    const float* rpb    = (const float*)d_in[5];
    const float* g1     = (const float*)d_in[6];
    const float* b1     = (const float*)d_in[7];
    const float* g2     = (const float*)d_in[8];
    const float* b2     = (const float*)d_in[9];
    const float* w1     = (const float*)d_in[10];
    const float* bb1    = (const float*)d_in[11];
    const float* w2     = (const float*)d_in[12];
    const float* bb2    = (const float*)d_in[13];
    float* out = (float*)d_out;

    float *h2;
    bf16 *qkv, *wq, *wp, *w1b, *w2b;
    cudaGetSymbolAddress((void**)&qkv, g_qkv);
    cudaGetSymbolAddress((void**)&h2,  g_h2);
    cudaGetSymbolAddress((void**)&wq,  g_wq);
    cudaGetSymbolAddress((void**)&wp,  g_wp);
    cudaGetSymbolAddress((void**)&w1b, g_w1);
    cudaGetSymbolAddress((void**)&w2b, g_w2);

    cudaFuncSetAttribute(qkv_kernel,      cudaFuncAttributeMaxDynamicSharedMemorySize, 81920);
    cudaFuncSetAttribute(attnproj_kernel, cudaFuncAttributeMaxDynamicSharedMemorySize, 65536);
    cudaFuncSetAttribute(mlp_kernel,      cudaFuncAttributeMaxDynamicSharedMemorySize, 98304);

    wconv_all<<<512, 256>>>(qkv_w, proj_w, w1, w2, wq, wp, w1b, w2b);

    qkv_kernel<<<TOK / 128, 256, 81920>>>(x, g1, b1, wq, qkv_b, qkv);
    attnproj_kernel<<<TOK / 128, 256, 65536>>>(qkv, rpb, wp, proj_b, x, h2);
    mlp_kernel<<<TOK / 64, 256, 98304>>>(h2, g2, b2, w1b, bb1, w2b, bb2, out);
}